// round 11
// baseline (speedup 1.0000x reference)
#include <cuda_runtime.h>
#include <math_constants.h>

#define NIMG 512
#define NCLS 20
#define RES 56
#define HW 3136            // 56*56
#define HWF4 (HW/4)        // 784
#define NENT 62720         // HW*NCLS
#define NPART 5
#define CPP 4              // classes per k1 CTA
#define ITEMS (CPP*HWF4)   // 3136 float4 per part
#define TOPK 1000
#define BUF 2048
#define SRT 1024
#define NT 512
#define CAPC 2048          // per-CTA exact-candidate buffer (>=0.5)
#define CAPL 2048          // per-CTA stage-1 candidate list
#define CAPI 12288         // per-image compact capacity (global)
#define KTH     0xBD4CCCCDu   // key(0.05f)
#define PREKEY  0xBF000000u   // key(0.5f) exact pre-filter for selection
#define KEY046  0xBEEB851Fu   // key(0.46f) argmax fallback guard
#define TOPBITS 0xBC000000u

__device__ float    g_ctrv[(size_t)NIMG * HW];
__device__ float    g_xcut[(size_t)NIMG * HW];   // logit(0.449/ctr) screen cutoff
__device__ unsigned g_hist[(size_t)NIMG * NPART * 2048];
__device__ unsigned long long g_cls[(size_t)NIMG * NCLS];
__device__ unsigned long long g_cand[(size_t)NIMG * CAPI];
__device__ unsigned g_ccnt[NIMG];
__device__ unsigned g_ovf[NIMG];
__device__ unsigned g_keys[(size_t)NIMG * NENT];   // FALLBACK ONLY

// Faithful replica of XLA:CPU's vectorized exp (Cephes/Eigen pexp<float>),
// UNFUSED mul/add rounding. DO NOT TOUCH — bit-exactness verified.
__device__ __forceinline__ float cephes_expf(float x){
    const float exp_hi = 88.3762626647950f;
    const float exp_lo = -88.3762626647949f;
    const float LOG2EF = 1.44269504088896341f;
    const float C1 = 0.693359375f;
    const float C2 = -2.12194440e-4f;
    float xc = fminf(fmaxf(x, exp_lo), exp_hi);
    float m = floorf(__fadd_rn(__fmul_rn(xc, LOG2EF), 0.5f));
    float r = __fsub_rn(xc, __fmul_rn(m, C1));
    r = __fsub_rn(r, __fmul_rn(m, C2));
    float r2 = __fmul_rn(r, r);
    float y = 1.9875691500e-4f;
    y = __fadd_rn(__fmul_rn(y, r), 1.3981999507e-3f);
    y = __fadd_rn(__fmul_rn(y, r), 8.3334519073e-3f);
    y = __fadd_rn(__fmul_rn(y, r), 4.1665795894e-2f);
    y = __fadd_rn(__fmul_rn(y, r), 1.6666665459e-1f);
    y = __fadd_rn(__fmul_rn(y, r), 5.0000001201e-1f);
    y = __fadd_rn(__fmul_rn(y, r2), r);
    y = __fadd_rn(y, 1.0f);
    int mi = (int)m;
    float sc = __int_as_float((mi + 127) << 23);
    return __fmul_rn(y, sc);
}

__device__ __forceinline__ float sig_x(float x){
    float e = cephes_expf(-x);
    return __fdiv_rn(1.0f, __fadd_rn(1.0f, e));
}

// Screen cutoff: x > xcut(c)  <=>  sigmoid(x)*c > ~0.449 (conservative).
__device__ __forceinline__ float xcut_of(float c){
    float ratio = 0.449f / c;
    if (!(ratio < 1.0f)) return CUDART_INF_F;   // c <= 0.449: never relevant
    return logf(ratio / (1.0f - ratio));        // logit; screen-only accuracy
}

// ============== Kernel 0: exact ctr sigmoids + screen cutoffs + init ==============
__global__ void __launch_bounds__(NT)
k0_ctr(const float* __restrict__ gctr)
{
    const int n = blockIdx.x;
    const float4* src = (const float4*)(gctr + (size_t)n * HW);
    float4* dst = (float4*)(g_ctrv + (size_t)n * HW);
    float4* xct = (float4*)(g_xcut + (size_t)n * HW);
    for (int i4 = threadIdx.x; i4 < HWF4; i4 += NT){
        float4 v = src[i4];
        float4 r;
        r.x = sig_x(v.x); r.y = sig_x(v.y);
        r.z = sig_x(v.z); r.w = sig_x(v.w);
        dst[i4] = r;
        float4 t;
        t.x = xcut_of(r.x); t.y = xcut_of(r.y);
        t.z = xcut_of(r.z); t.w = xcut_of(r.w);
        xct[i4] = t;
    }
    if (threadIdx.x == 0){ g_ccnt[n] = 0u; g_ovf[n] = 0u; }
}

// ============== Kernel 1: compare-only screen -> dense exact eval ==============
__global__ void __launch_bounds__(NT)
k1_keys(const float* __restrict__ gcls)
{
    __shared__ unsigned s_hist[2048];
    __shared__ unsigned long long s_buf[CAPC];    // exact packed cands (key>=0.5)
    __shared__ unsigned long long s_cand[CAPL];   // (partLocalIdx<<32)|xbits
    __shared__ unsigned long long s_cls[CPP];
    __shared__ unsigned s_cc, s_nc, s_base;

    const int part = blockIdx.x;
    const int n    = blockIdx.y;
    const int tid  = threadIdx.x;
    const int lane = tid & 31;
    const float* cls = gcls + (size_t)n * NENT;
    const float* ctrv = g_ctrv + (size_t)n * HW;
    const float4* colBase = (const float4*)(cls + part * (CPP * HW));
    const float4* xct4 = (const float4*)(g_xcut + (size_t)n * HW);

    for (int i = tid; i < 2048; i += NT) s_hist[i] = 0u;
    if (tid < CPP) s_cls[tid] = 0ULL;
    if (tid == 0){ s_cc = 0u; s_nc = 0u; }
    __syncthreads();

    // ---- Stage 1: screen = one compare per element, batched loads for MLP
    #pragma unroll 1
    for (int g = 0; g < 2; g++){
        float4 v[4], tv[4];
        int    tt[4];
        #pragma unroll
        for (int k = 0; k < 4; k++){
            int t = tid + (g * 4 + k) * NT;
            tt[k] = t;
            bool ib = (t < ITEMS);
            int tm = t;
            if (tm >= 2 * HWF4) tm -= 2 * HWF4;
            if (tm >= HWF4)     tm -= HWF4;
            v[k]  = ib ? colBase[t] : make_float4(-1e9f, -1e9f, -1e9f, -1e9f);
            tv[k] = ib ? xct4[tm]   : make_float4(CUDART_INF_F, CUDART_INF_F,
                                                  CUDART_INF_F, CUDART_INF_F);
        }
        #pragma unroll
        for (int k = 0; k < 4; k++){
            #pragma unroll
            for (int j = 0; j < 4; j++){
                float x  = j == 0 ? v[k].x  : j == 1 ? v[k].y  : j == 2 ? v[k].z  : v[k].w;
                float xc = j == 0 ? tv[k].x : j == 1 ? tv[k].y : j == 2 ? tv[k].z : tv[k].w;
                if (x > xc){
                    unsigned p = atomicAdd(&s_nc, 1u);
                    if (p < CAPL){
                        unsigned idx = (unsigned)(4 * tt[k] + j);   // part-local
                        s_cand[p] = ((unsigned long long)idx << 32)
                                  | (unsigned long long)__float_as_uint(x);
                    }
                }
            }
        }
    }
    __syncthreads();

    unsigned ncRaw = s_nc;
    bool listOvf = (ncRaw > CAPL);
    int nc = listOvf ? CAPL : (int)ncRaw;

    // ---- Stage 2: dense exact evaluation of candidates (no collectives)
    if (!listOvf){
        for (int i = tid; i < nc; i += NT){
            unsigned long long e = s_cand[i];
            int idx = (int)(e >> 32);
            float x = __uint_as_float((unsigned)e);
            int cc = idx / HW;
            int loc = idx - cc * HW;
            float sv = __fmul_rn(sig_x(x), ctrv[loc]);
            unsigned key = __float_as_uint(sv) | 0x80000000u;
            unsigned long long pk = ((unsigned long long)key << 32) | (unsigned)(HW - 1 - loc);
            atomicMax(&s_cls[cc], pk);
            if (key >= PREKEY){
                unsigned bin = (key - PREKEY) >> 12;
                if (bin > 2047u) bin = 2047u;
                atomicAdd(&s_hist[bin], 1u);
                unsigned p = atomicAdd(&s_cc, 1u);
                if (p < CAPC){
                    int f = loc * NCLS + (part * CPP + cc);
                    s_buf[p] = ((unsigned long long)key << 17) | (unsigned)(NENT - f);
                }
            }
        }
    }
    __syncthreads();

    // ---- Guarded fallbacks: dense exact argmax if class max < 0.46 or list overflow
    #pragma unroll
    for (int cc = 0; cc < CPP; cc++){
        bool need = listOvf || ((unsigned)(s_cls[cc] >> 32) < KEY046);
        if (need){
            const int c = part * CPP + cc;
            const float* colp = cls + c * HW;
            unsigned long long best = 0ULL;
            for (int loc = tid; loc < HW; loc += NT){
                float sv = __fmul_rn(sig_x(colp[loc]), ctrv[loc]);
                unsigned key = __float_as_uint(sv) | 0x80000000u;
                unsigned long long pk = ((unsigned long long)key << 32) | (unsigned)(HW - 1 - loc);
                if (pk > best) best = pk;
            }
            #pragma unroll
            for (int off = 16; off; off >>= 1){
                unsigned long long o = __shfl_down_sync(0xffffffffu, best, off);
                if (o > best) best = o;
            }
            if (lane == 0) atomicMax(&s_cls[cc], best);
        }
    }
    __syncthreads();

    unsigned* gh = g_hist + ((size_t)n * NPART + part) * 2048;
    for (int i = tid; i < 2048; i += NT) gh[i] = s_hist[i];
    if (tid < CPP) g_cls[(size_t)n * NCLS + part * CPP + tid] = s_cls[tid];

    unsigned ccN = s_cc;
    bool ovf = listOvf || (ccN > CAPC);
    if (ccN > CAPC) ccN = CAPC;
    if (tid == 0) s_base = atomicAdd(&g_ccnt[n], ccN);
    __syncthreads();
    unsigned base = s_base;
    unsigned long long* cand = g_cand + (size_t)n * CAPI;
    for (unsigned i = tid; i < ccN; i += NT){
        unsigned p = base + i;
        if (p < CAPI) cand[p] = s_buf[i];
        else ovf = true;
    }
    if (ovf) g_ovf[n] = 1u;
}

// ============== shared helper ==============
__device__ void find_cross2048(unsigned* s_hist, unsigned* s_scan, unsigned K,
                               unsigned* s_b, unsigned* s_above, unsigned* s_total)
{
    const int tid = threadIdx.x;
    const int top = 2047 - tid * 4;
    unsigned part = 0;
    #pragma unroll
    for (int j = 0; j < 4; j++) part += s_hist[top - j];
    s_scan[tid] = part;
    __syncthreads();
    for (int off = 1; off < NT; off <<= 1){
        unsigned v = (tid >= off) ? s_scan[tid - off] : 0u;
        __syncthreads();
        s_scan[tid] += v;
        __syncthreads();
    }
    unsigned incl = s_scan[tid];
    unsigned excl = incl - part;
    if (tid == NT - 1) *s_total = incl;
    if (excl < K && incl >= K){
        unsigned run = excl;
        #pragma unroll
        for (int j = 0; j < 4; j++){
            int b = top - j;
            unsigned h = s_hist[b];
            if (run + h >= K){ *s_b = (unsigned)b; *s_above = run; break; }
            run += h;
        }
    }
    __syncthreads();
}

// ============== Kernel 2: threshold + collect + prune + sort + decode ==============
__global__ void __launch_bounds__(NT)
k2_select(const float* __restrict__ gcls, const float* __restrict__ greg,
          const float* __restrict__ gbox, const float* __restrict__ gps,
          float* __restrict__ out)
{
    __shared__ unsigned s_hist[2048];
    __shared__ unsigned s_scan[NT];
    __shared__ unsigned long long s_keys[BUF];
    __shared__ unsigned long long s_out[SRT];
    __shared__ unsigned s_b, s_above, s_total;
    __shared__ int s_cnt, s_cnt2, s_fill, s_tot2;
    __shared__ unsigned s_wcnt[NT/32], s_woff[NT/32];

    const int n    = blockIdx.x;
    const int tid  = threadIdx.x;
    const int lane = tid & 31;
    const int wrp  = tid >> 5;
    const float* reg = greg + (size_t)n * 4 * HW;
    const unsigned long long* cand = g_cand + (size_t)n * CAPI;

    {
        const unsigned* gh = g_hist + (size_t)n * NPART * 2048;
        for (int b = tid; b < 2048; b += NT){
            unsigned s = 0;
            #pragma unroll
            for (int p = 0; p < NPART; p++) s += gh[p * 2048 + b];
            s_hist[b] = s;
        }
    }
    if (tid == 0){ s_b = 0xFFFFFFFFu; s_cnt = 0; s_cnt2 = 0; }
    __syncthreads();

    find_cross2048(s_hist, s_scan, TOPK, &s_b, &s_above, &s_total);
    bool fast = (s_b != 0xFFFFFFFFu) && (g_ovf[n] == 0u);
    unsigned cum1 = 0;
    if (fast){
        cum1 = s_above + s_hist[s_b];
        fast = (cum1 <= BUF);
    }
    unsigned b0f = s_b;
    __syncthreads();

    int cnt;
    if (fast){
        unsigned T = PREKEY + (b0f << 12);
        unsigned long long pthr = ((unsigned long long)T) << 17;
        int ccnt = (int)g_ccnt[n];
        if (ccnt > CAPI) ccnt = CAPI;
        for (int i = tid; i < ccnt; i += NT){
            unsigned long long e = cand[i];
            if (e >= pthr) s_keys[atomicAdd(&s_cnt, 1)] = e;
        }
        __syncthreads();
        cnt = s_cnt;
    } else {
        // ---- FALLBACK: full exact recompute + radix select (general data)
        const float* cls = gcls + (size_t)n * NENT;
        const float* ctrv = g_ctrv + (size_t)n * HW;
        unsigned* keys = g_keys + (size_t)n * NENT;
        if (tid == 0) s_tot2 = 0;
        for (int i = tid; i < 2048; i += NT) s_hist[i] = 0u;
        __syncthreads();
        int totL = 0;
        for (int i = tid; i < NENT; i += NT){
            int c = i / HW;
            int loc = i - c * HW;
            float sv = __fmul_rn(sig_x(cls[i]), ctrv[loc]);
            unsigned ok = __float_as_uint(sv) | 0x80000000u;
            keys[i] = ok;
            if (ok > KTH){ totL++; atomicAdd(&s_hist[(ok >> 15) & 0x7FFu], 1u); }
        }
        #pragma unroll
        for (int off = 16; off; off >>= 1) totL += __shfl_down_sync(0xffffffffu, totL, off);
        if (lane == 0) atomicAdd(&s_tot2, totL);
        if (tid == 0) s_b = 0xFFFFFFFFu;
        __syncthreads();
        int total = s_tot2;

        find_cross2048(s_hist, s_scan, TOPK, &s_b, &s_above, &s_total);
        int mode; unsigned T = 0; int needed = 0;
        if (total < TOPK){
            mode = 2; T = 0u; needed = TOPK - total;
        } else {
            unsigned b0 = s_b;
            unsigned above1 = s_above;
            unsigned c1 = above1 + s_hist[b0];
            __syncthreads();
            if (c1 <= BUF){
                mode = 0; T = TOPBITS | (b0 << 15);
            } else {
                for (int i = tid; i < 2048; i += NT) s_hist[i] = 0u;
                __syncthreads();
                for (int i = tid; i < NENT; i += NT){
                    unsigned ok = keys[i];
                    if (ok > KTH && ((ok >> 15) & 0x7FFu) == b0)
                        atomicAdd(&s_hist[(ok >> 4) & 0x7FFu], 1u);
                }
                __syncthreads();
                find_cross2048(s_hist, s_scan, TOPK - above1, &s_b, &s_above, &s_total);
                unsigned b1 = s_b;
                unsigned above2 = above1 + s_above;
                unsigned c2 = above2 + s_hist[b1];
                __syncthreads();
                if (c2 <= BUF){
                    mode = 0; T = TOPBITS | (b0 << 15) | (b1 << 4);
                } else {
                    if (tid < 16) s_hist[tid] = 0u;
                    __syncthreads();
                    unsigned winhi = (TOPBITS | (b0 << 15) | (b1 << 4)) >> 4;
                    for (int i = tid; i < NENT; i += NT){
                        unsigned ok = keys[i];
                        if (ok > KTH && (ok >> 4) == winhi)
                            atomicAdd(&s_hist[ok & 0xFu], 1u);
                    }
                    __syncthreads();
                    if (tid == 0){
                        unsigned K3 = TOPK - above2, run = 0;
                        for (int b = 15; b >= 0; b--){
                            unsigned h = s_hist[b];
                            if (run + h >= K3){ s_b = (unsigned)b; s_above = run; break; }
                            run += h;
                        }
                    }
                    __syncthreads();
                    unsigned b2 = s_b;
                    unsigned above3 = above2 + s_above;
                    unsigned c3 = above3 + s_hist[b2];
                    __syncthreads();
                    T = TOPBITS | (b0 << 15) | (b1 << 4) | b2;
                    if (c3 <= BUF) mode = 0;
                    else { mode = 1; needed = TOPK - (int)above3; }
                }
            }
        }
        for (int i = tid; i < NENT; i += NT){
            unsigned ok = keys[i];
            bool take = (ok > KTH) && (mode == 1 ? (ok > T) : (ok >= T));
            if (take){
                int c = i / HW;
                int loc = i - c * HW;
                int f = loc * NCLS + c;
                s_keys[atomicAdd(&s_cnt, 1)] = ((unsigned long long)ok << 17) | (unsigned)(NENT - f);
            }
        }
        __syncthreads();
        cnt = s_cnt;
        if (mode != 0){
            if (tid == 0) s_fill = 0;
            __syncthreads();
            unsigned fillHigh = (mode == 1) ? T : 0u;
            for (int fb = 0; fb < NENT; fb += NT){
                int f = fb + tid;
                bool eq = false;
                if (f < NENT){
                    int loc = f / NCLS;
                    int c = f - loc * NCLS;
                    unsigned ok = keys[c * HW + loc];
                    eq = (mode == 1) ? (ok == T) : (ok <= KTH);
                }
                unsigned bal = __ballot_sync(0xffffffffu, eq);
                if (lane == 0) s_wcnt[wrp] = (unsigned)__popc(bal);
                __syncthreads();
                if (tid == 0){
                    unsigned run = (unsigned)s_fill;
                    #pragma unroll
                    for (int i = 0; i < NT/32; i++){ s_woff[i] = run; run += s_wcnt[i]; }
                    s_fill = (int)run;
                }
                __syncthreads();
                if (eq){
                    int rank = (int)s_woff[wrp] + __popc(bal & ((1u << lane) - 1u));
                    if (rank < needed)
                        s_keys[cnt + rank] = ((unsigned long long)fillHigh << 17) | (unsigned)(NENT - f);
                }
                if (s_fill >= needed) break;
            }
            cnt = TOPK;
            __syncthreads();
        }
    }

    // ---- Prune to <= 1024 (rare)
    if (cnt > SRT){
        unsigned long long hi = 0;
        int K = TOPK, above = 0;
        unsigned long long thresholdP = 0;
        #pragma unroll 1
        for (int l = 0; l < 5; l++){
            const int sh = (l==0)?38:(l==1)?27:(l==2)?16:(l==3)?5:0;
            const int wb = (l==4)?5:11;
            for (int i = tid; i < 2048; i += NT) s_hist[i] = 0u;
            __syncthreads();
            for (int i = tid; i < cnt; i += NT){
                unsigned long long p = s_keys[i];
                if ((p >> (sh + wb)) == hi)
                    atomicAdd(&s_hist[(unsigned)((p >> sh) & ((1u << wb) - 1u))], 1u);
            }
            __syncthreads();
            find_cross2048(s_hist, s_scan, (unsigned)K, &s_b, &s_above, &s_total);
            unsigned b = s_b, aw = s_above, hb = s_hist[b];
            __syncthreads();
            if (above + (int)aw + (int)hb <= SRT){
                thresholdP = ((hi << wb) | b) << sh;
                break;
            }
            above += (int)aw; K -= (int)aw; hi = (hi << wb) | b;
        }
        for (int base = 0; base < cnt; base += NT){
            int i = base + tid;
            bool take = (i < cnt) && (s_keys[i] >= thresholdP);
            unsigned bal = __ballot_sync(0xffffffffu, take);
            if (bal){
                int ldr = __ffs(bal) - 1;
                int basep = 0;
                if (lane == ldr) basep = atomicAdd(&s_cnt2, __popc(bal));
                basep = __shfl_sync(0xffffffffu, basep, ldr);
                if (take)
                    s_out[basep + __popc(bal & ((1u << lane) - 1u))] = s_keys[i];
            }
        }
        __syncthreads();
        int c2 = s_cnt2;
        for (int i = tid; i < SRT; i += NT)
            if (i >= c2) s_out[i] = 0ULL;
    } else {
        for (int i = tid; i < SRT; i += NT)
            s_out[i] = (i < cnt) ? s_keys[i] : 0ULL;
    }
    __syncthreads();

    // ---- Bitonic sort, descending, 1024 u64
    for (unsigned k = 2; k <= SRT; k <<= 1){
        for (unsigned j = k >> 1; j > 0; j >>= 1){
            #pragma unroll
            for (int t = 0; t < SRT/NT; t++){
                int i = tid + t * NT;
                unsigned ixj = (unsigned)i ^ j;
                if (ixj > (unsigned)i){
                    unsigned long long a = s_out[i];
                    unsigned long long b = s_out[ixj];
                    bool desc = ((i & k) == 0);
                    if (desc ? (a < b) : (a > b)){
                        s_out[i] = b; s_out[ixj] = a;
                    }
                }
            }
            __syncthreads();
        }
    }

    // ---- Decode + write outputs (rounding-pinned; verified bit-exact)
    const size_t detB = 0;
    const size_t scB  = (size_t)NIMG * TOPK * 4;
    const size_t lbB  = scB + (size_t)NIMG * TOPK;
    const size_t vaB  = lbB + (size_t)NIMG * TOPK;
    const size_t hdB  = vaB + (size_t)NIMG * TOPK;
    const size_t hsB  = hdB + (size_t)NIMG * NCLS * 4;
    const float bx = gbox[n*4+0], by = gbox[n*4+1];
    const float sx = __fsub_rn(gbox[n*4+2], bx);
    const float sy = __fsub_rn(gbox[n*4+3], by);
    const float ps = gps[n];

    for (int i = tid; i < TOPK; i += NT){
        unsigned long long e = s_out[i];
        unsigned ok = (unsigned)(e >> 17);
        int f = NENT - (int)(e & 0x1FFFFu);
        int loc = f / NCLS;
        int c = f - loc * NCLS;
        int h = loc / RES, w = loc - h * RES;
        float lx = w + 0.5f, ly = h + 0.5f;
        float r0 = reg[loc], r1 = reg[HW + loc], r2 = reg[2*HW + loc], r3 = reg[3*HW + loc];
        float x1 = __fadd_rn(__fmul_rn(__fdiv_rn(__fsub_rn(lx, r0), 56.0f), sx), bx);
        float y1 = __fadd_rn(__fmul_rn(__fdiv_rn(__fsub_rn(ly, r1), 56.0f), sy), by);
        float x2 = __fadd_rn(__fmul_rn(__fdiv_rn(__fadd_rn(lx, r2), 56.0f), sx), bx);
        float y2 = __fadd_rn(__fmul_rn(__fdiv_rn(__fadd_rn(ly, r3), 56.0f), sy), by);
        x1 = fminf(fmaxf(x1, 0.0f), 1332.0f);
        x2 = fminf(fmaxf(x2, 0.0f), 1332.0f);
        y1 = fminf(fmaxf(y1, 0.0f),  799.0f);
        y2 = fminf(fmaxf(y2, 0.0f),  799.0f);
        bool valid = (ok > KTH) && (__fsub_rn(x2, x1) >= 0.0f) && (__fsub_rn(y2, y1) >= 0.0f);
        float val = __uint_as_float(ok ^ 0x80000000u);
        float sc = valid ? __fsqrt_rn(__fmul_rn(__fsqrt_rn(val), ps)) : 0.0f;
        size_t row = (size_t)n * TOPK + i;
        out[detB + row*4 + 0] = x1;
        out[detB + row*4 + 1] = y1;
        out[detB + row*4 + 2] = x2;
        out[detB + row*4 + 3] = y2;
        out[scB + row] = sc;
        out[lbB + row] = (float)(c + 2);
        out[vaB + row] = valid ? 1.0f : 0.0f;
    }

    if (tid < NCLS){
        unsigned long long e = g_cls[(size_t)n * NCLS + tid];
        unsigned ok = (unsigned)(e >> 32);
        int loc = HW - 1 - (int)(e & 0xFFFFFFFFu);
        int h = loc / RES, w = loc - h * RES;
        float lx = w + 0.5f, ly = h + 0.5f;
        float r0 = reg[loc], r1 = reg[HW + loc], r2 = reg[2*HW + loc], r3 = reg[3*HW + loc];
        float x1 = __fadd_rn(__fmul_rn(__fdiv_rn(__fsub_rn(lx, r0), 56.0f), sx), bx);
        float y1 = __fadd_rn(__fmul_rn(__fdiv_rn(__fsub_rn(ly, r1), 56.0f), sy), by);
        float x2 = __fadd_rn(__fmul_rn(__fdiv_rn(__fadd_rn(lx, r2), 56.0f), sx), bx);
        float y2 = __fadd_rn(__fmul_rn(__fdiv_rn(__fadd_rn(ly, r3), 56.0f), sy), by);
        float hv = __uint_as_float(ok ^ 0x80000000u);
        float hs = (hv >= 0.9f) ? __fsqrt_rn(__fmul_rn(__fsqrt_rn(hv), ps)) : 0.0f;
        size_t rr = (size_t)n * NCLS + tid;
        out[hdB + rr*4 + 0] = x1;
        out[hdB + rr*4 + 1] = y1;
        out[hdB + rr*4 + 2] = x2;
        out[hdB + rr*4 + 3] = y2;
        out[hsB + rr] = hs;
    }
}

extern "C" void kernel_launch(void* const* d_in, const int* in_sizes, int n_in,
                              void* d_out, int out_size)
{
    const float *bcls = nullptr, *breg = nullptr, *bctr = nullptr,
                *bbox = nullptr, *bps = nullptr;
    for (int i = 0; i < n_in; i++){
        switch (in_sizes[i]){
            case 32112640: bcls = (const float*)d_in[i]; break;
            case 6422528:  breg = (const float*)d_in[i]; break;
            case 1605632:  bctr = (const float*)d_in[i]; break;
            case 2048:     bbox = (const float*)d_in[i]; break;
            case 512:      bps  = (const float*)d_in[i]; break;
            default: break;
        }
    }
    (void)out_size;
    k0_ctr<<<NIMG, NT>>>(bctr);
    k1_keys<<<dim3(NPART, NIMG), NT>>>(bcls);
    k2_select<<<NIMG, NT>>>(bcls, breg, bbox, bps, (float*)d_out);
}

// round 12
// speedup vs baseline: 1.0622x; 1.0622x over previous
#include <cuda_runtime.h>
#include <math_constants.h>

#define NIMG 512
#define NCLS 20
#define RES 56
#define HW 3136            // 56*56
#define HWF4 (HW/4)        // 784
#define NENT 62720         // HW*NCLS
#define NPART 5
#define CPP 4              // classes per k1 CTA
#define TOPK 1000
#define BUF 2048
#define SRT 1024
#define NT 512
#define CAPC 2048          // per-CTA exact-candidate buffer (>=0.5)
#define CAPL 2048          // per-CTA stage-1 candidate list
#define CAPI 12288         // per-image compact capacity (global)
#define KTH     0xBD4CCCCDu   // key(0.05f)
#define PREKEY  0xBF000000u   // key(0.5f) exact pre-filter for selection
#define KEY046  0xBEEB851Fu   // key(0.46f) argmax fallback guard
#define TOPBITS 0xBC000000u

__device__ float    g_ctrv[(size_t)NIMG * HW];
__device__ float    g_xcut[(size_t)NIMG * HW];   // logit(0.449/ctr) screen cutoff
__device__ unsigned g_hist[(size_t)NIMG * NPART * 2048];
__device__ unsigned long long g_cls[(size_t)NIMG * NCLS];
__device__ unsigned long long g_cand[(size_t)NIMG * CAPI];
__device__ unsigned g_ccnt[NIMG];
__device__ unsigned g_ovf[NIMG];
__device__ unsigned g_keys[(size_t)NIMG * NENT];   // FALLBACK ONLY

// Faithful replica of XLA:CPU's vectorized exp (Cephes/Eigen pexp<float>),
// UNFUSED mul/add rounding. DO NOT TOUCH — bit-exactness verified.
__device__ __forceinline__ float cephes_expf(float x){
    const float exp_hi = 88.3762626647950f;
    const float exp_lo = -88.3762626647949f;
    const float LOG2EF = 1.44269504088896341f;
    const float C1 = 0.693359375f;
    const float C2 = -2.12194440e-4f;
    float xc = fminf(fmaxf(x, exp_lo), exp_hi);
    float m = floorf(__fadd_rn(__fmul_rn(xc, LOG2EF), 0.5f));
    float r = __fsub_rn(xc, __fmul_rn(m, C1));
    r = __fsub_rn(r, __fmul_rn(m, C2));
    float r2 = __fmul_rn(r, r);
    float y = 1.9875691500e-4f;
    y = __fadd_rn(__fmul_rn(y, r), 1.3981999507e-3f);
    y = __fadd_rn(__fmul_rn(y, r), 8.3334519073e-3f);
    y = __fadd_rn(__fmul_rn(y, r), 4.1665795894e-2f);
    y = __fadd_rn(__fmul_rn(y, r), 1.6666665459e-1f);
    y = __fadd_rn(__fmul_rn(y, r), 5.0000001201e-1f);
    y = __fadd_rn(__fmul_rn(y, r2), r);
    y = __fadd_rn(y, 1.0f);
    int mi = (int)m;
    float sc = __int_as_float((mi + 127) << 23);
    return __fmul_rn(y, sc);
}

__device__ __forceinline__ float sig_x(float x){
    float e = cephes_expf(-x);
    return __fdiv_rn(1.0f, __fadd_rn(1.0f, e));
}

// Screen cutoff: x > xcut(c)  <=>  sigmoid(x)*c > ~0.449 (conservative).
__device__ __forceinline__ float xcut_of(float c){
    float ratio = 0.449f / c;
    if (!(ratio < 1.0f)) return CUDART_INF_F;   // c <= 0.449: never relevant
    return logf(ratio / (1.0f - ratio));        // logit; screen-only accuracy
}

// ============== Kernel 0: exact ctr sigmoids + screen cutoffs + init ==============
__global__ void __launch_bounds__(NT)
k0_ctr(const float* __restrict__ gctr)
{
    const int n = blockIdx.x;
    const float4* src = (const float4*)(gctr + (size_t)n * HW);
    float4* dst = (float4*)(g_ctrv + (size_t)n * HW);
    float4* xct = (float4*)(g_xcut + (size_t)n * HW);
    for (int i4 = threadIdx.x; i4 < HWF4; i4 += NT){
        float4 v = src[i4];
        float4 r;
        r.x = sig_x(v.x); r.y = sig_x(v.y);
        r.z = sig_x(v.z); r.w = sig_x(v.w);
        dst[i4] = r;
        float4 t;
        t.x = xcut_of(r.x); t.y = xcut_of(r.y);
        t.z = xcut_of(r.z); t.w = xcut_of(r.w);
        xct[i4] = t;
    }
    if (threadIdx.x == 0){ g_ccnt[n] = 0u; g_ovf[n] = 0u; }
}

// ============== Kernel 1: compare screen (warp-aggregated) -> dense exact eval ==============
__global__ void __launch_bounds__(NT, 2)
k1_keys(const float* __restrict__ gcls)
{
    __shared__ unsigned s_hist[2048];
    __shared__ unsigned long long s_buf[CAPC];    // exact packed cands (key>=0.5)
    __shared__ unsigned long long s_cand[CAPL];   // (partLocalIdx<<32)|xbits
    __shared__ unsigned long long s_cls[CPP];
    __shared__ unsigned s_cc, s_nc, s_base;

    const int part = blockIdx.x;
    const int n    = blockIdx.y;
    const int tid  = threadIdx.x;
    const int lane = tid & 31;
    const float* cls = gcls + (size_t)n * NENT;
    const float* ctrv = g_ctrv + (size_t)n * HW;
    const float4* colBase = (const float4*)(cls + part * (CPP * HW));
    const float4* xct4 = (const float4*)(g_xcut + (size_t)n * HW);

    for (int i = tid; i < 2048; i += NT) s_hist[i] = 0u;
    if (tid < CPP) s_cls[tid] = 0ULL;
    if (tid == 0){ s_cc = 0u; s_nc = 0u; }
    __syncthreads();

    // ---- Stage 1: 10 batched independent LDG.128 (2 loc-chunks × [1 xcut + 4 class]),
    //      screen = 1 compare/elem, warp-scan aggregated append (1 atomic/warp).
    float4 xc[2], d[2][CPP];
    #pragma unroll
    for (int w = 0; w < 2; w++){
        int lc = tid + w * NT;
        bool ib = (lc < HWF4);
        xc[w] = ib ? xct4[lc] : make_float4(CUDART_INF_F, CUDART_INF_F,
                                            CUDART_INF_F, CUDART_INF_F);
        #pragma unroll
        for (int c = 0; c < CPP; c++)
            d[w][c] = ib ? colBase[c * HWF4 + lc]
                         : make_float4(-1e9f, -1e9f, -1e9f, -1e9f);
    }
    unsigned hm = 0;
    #pragma unroll
    for (int w = 0; w < 2; w++){
        #pragma unroll
        for (int c = 0; c < CPP; c++){
            #pragma unroll
            for (int j = 0; j < 4; j++){
                float x  = j==0 ? d[w][c].x : j==1 ? d[w][c].y : j==2 ? d[w][c].z : d[w][c].w;
                float cu = j==0 ? xc[w].x   : j==1 ? xc[w].y   : j==2 ? xc[w].z   : xc[w].w;
                if (x > cu) hm |= 1u << (w * 16 + c * 4 + j);
            }
        }
    }
    {
        unsigned h = (unsigned)__popc(hm);
        unsigned incl = h;
        #pragma unroll
        for (int off = 1; off < 32; off <<= 1){
            unsigned t = __shfl_up_sync(0xffffffffu, incl, off);
            if (lane >= off) incl += t;
        }
        unsigned wtot = __shfl_sync(0xffffffffu, incl, 31);
        unsigned wbase = 0;
        if (wtot){
            if (lane == 31) wbase = atomicAdd(&s_nc, wtot);
            wbase = __shfl_sync(0xffffffffu, wbase, 31);
        }
        unsigned p = wbase + incl - h;
        if (hm){
            #pragma unroll
            for (int w = 0; w < 2; w++){
                #pragma unroll
                for (int c = 0; c < CPP; c++){
                    #pragma unroll
                    for (int j = 0; j < 4; j++){
                        if (hm & (1u << (w * 16 + c * 4 + j))){
                            float x = j==0 ? d[w][c].x : j==1 ? d[w][c].y : j==2 ? d[w][c].z : d[w][c].w;
                            if (p < CAPL){
                                unsigned idx = (unsigned)(c * HW + 4 * (tid + w * NT) + j);
                                s_cand[p] = ((unsigned long long)idx << 32)
                                          | (unsigned long long)__float_as_uint(x);
                            }
                            p++;
                        }
                    }
                }
            }
        }
    }
    __syncthreads();

    unsigned ncRaw = s_nc;
    bool listOvf = (ncRaw > CAPL);
    int nc = listOvf ? CAPL : (int)ncRaw;

    // ---- Stage 2: dense exact evaluation, ballot-aggregated append
    if (!listOvf){
        for (int base = 0; base < nc; base += NT){
            int i = base + tid;
            bool on = (i < nc);
            unsigned long long e = on ? s_cand[i] : 0ULL;
            int idx = (int)(e >> 32);
            float x = __uint_as_float((unsigned)e);
            int cc = idx / HW;
            int loc = idx - cc * HW;
            unsigned key = 0;
            if (on){
                float sv = __fmul_rn(sig_x(x), ctrv[loc]);
                key = __float_as_uint(sv) | 0x80000000u;
                unsigned long long pk = ((unsigned long long)key << 32) | (unsigned)(HW - 1 - loc);
                if (pk > *((volatile unsigned long long*)&s_cls[cc]))
                    atomicMax(&s_cls[cc], pk);
                if (key >= PREKEY){
                    unsigned bin = (key - PREKEY) >> 12;
                    if (bin > 2047u) bin = 2047u;
                    atomicAdd(&s_hist[bin], 1u);
                }
            }
            bool sel = on && (key >= PREKEY);
            unsigned bal = __ballot_sync(0xffffffffu, sel);
            if (bal){
                int ldr = __ffs(bal) - 1;
                unsigned basep = 0;
                if (lane == ldr) basep = atomicAdd(&s_cc, (unsigned)__popc(bal));
                basep = __shfl_sync(0xffffffffu, basep, ldr);
                if (sel){
                    unsigned p = basep + (unsigned)__popc(bal & ((1u << lane) - 1u));
                    if (p < CAPC){
                        int f = loc * NCLS + (part * CPP + cc);
                        s_buf[p] = ((unsigned long long)key << 17) | (unsigned)(NENT - f);
                    }
                }
            }
        }
    }
    __syncthreads();

    // ---- Guarded fallbacks: dense exact argmax if class max < 0.46 or list overflow
    #pragma unroll
    for (int cc = 0; cc < CPP; cc++){
        bool need = listOvf || ((unsigned)(s_cls[cc] >> 32) < KEY046);
        if (need){
            const int c = part * CPP + cc;
            const float* colp = cls + c * HW;
            unsigned long long best = 0ULL;
            for (int loc = tid; loc < HW; loc += NT){
                float sv = __fmul_rn(sig_x(colp[loc]), ctrv[loc]);
                unsigned key = __float_as_uint(sv) | 0x80000000u;
                unsigned long long pk = ((unsigned long long)key << 32) | (unsigned)(HW - 1 - loc);
                if (pk > best) best = pk;
            }
            #pragma unroll
            for (int off = 16; off; off >>= 1){
                unsigned long long o = __shfl_down_sync(0xffffffffu, best, off);
                if (o > best) best = o;
            }
            if (lane == 0) atomicMax(&s_cls[cc], best);
        }
    }
    __syncthreads();

    unsigned* gh = g_hist + ((size_t)n * NPART + part) * 2048;
    for (int i = tid; i < 2048; i += NT) gh[i] = s_hist[i];
    if (tid < CPP) g_cls[(size_t)n * NCLS + part * CPP + tid] = s_cls[tid];

    unsigned ccN = s_cc;
    bool ovf = listOvf || (ccN > CAPC);
    if (ccN > CAPC) ccN = CAPC;
    if (tid == 0) s_base = atomicAdd(&g_ccnt[n], ccN);
    __syncthreads();
    unsigned base = s_base;
    unsigned long long* cand = g_cand + (size_t)n * CAPI;
    for (unsigned i = tid; i < ccN; i += NT){
        unsigned p = base + i;
        if (p < CAPI) cand[p] = s_buf[i];
        else ovf = true;
    }
    if (ovf) g_ovf[n] = 1u;
}

// ============== shared helper ==============
__device__ void find_cross2048(unsigned* s_hist, unsigned* s_scan, unsigned K,
                               unsigned* s_b, unsigned* s_above, unsigned* s_total)
{
    const int tid = threadIdx.x;
    const int top = 2047 - tid * 4;
    unsigned part = 0;
    #pragma unroll
    for (int j = 0; j < 4; j++) part += s_hist[top - j];
    s_scan[tid] = part;
    __syncthreads();
    for (int off = 1; off < NT; off <<= 1){
        unsigned v = (tid >= off) ? s_scan[tid - off] : 0u;
        __syncthreads();
        s_scan[tid] += v;
        __syncthreads();
    }
    unsigned incl = s_scan[tid];
    unsigned excl = incl - part;
    if (tid == NT - 1) *s_total = incl;
    if (excl < K && incl >= K){
        unsigned run = excl;
        #pragma unroll
        for (int j = 0; j < 4; j++){
            int b = top - j;
            unsigned h = s_hist[b];
            if (run + h >= K){ *s_b = (unsigned)b; *s_above = run; break; }
            run += h;
        }
    }
    __syncthreads();
}

// ============== Kernel 2: threshold + collect + prune + sort + decode ==============
__global__ void __launch_bounds__(NT)
k2_select(const float* __restrict__ gcls, const float* __restrict__ greg,
          const float* __restrict__ gbox, const float* __restrict__ gps,
          float* __restrict__ out)
{
    __shared__ unsigned s_hist[2048];
    __shared__ unsigned s_scan[NT];
    __shared__ unsigned long long s_keys[BUF];
    __shared__ unsigned long long s_out[SRT];
    __shared__ unsigned s_b, s_above, s_total;
    __shared__ int s_cnt, s_cnt2, s_fill, s_tot2;
    __shared__ unsigned s_wcnt[NT/32], s_woff[NT/32];

    const int n    = blockIdx.x;
    const int tid  = threadIdx.x;
    const int lane = tid & 31;
    const int wrp  = tid >> 5;
    const float* reg = greg + (size_t)n * 4 * HW;
    const unsigned long long* cand = g_cand + (size_t)n * CAPI;

    {
        const unsigned* gh = g_hist + (size_t)n * NPART * 2048;
        for (int b = tid; b < 2048; b += NT){
            unsigned s = 0;
            #pragma unroll
            for (int p = 0; p < NPART; p++) s += gh[p * 2048 + b];
            s_hist[b] = s;
        }
    }
    if (tid == 0){ s_b = 0xFFFFFFFFu; s_cnt = 0; s_cnt2 = 0; }
    __syncthreads();

    find_cross2048(s_hist, s_scan, TOPK, &s_b, &s_above, &s_total);
    bool fast = (s_b != 0xFFFFFFFFu) && (g_ovf[n] == 0u);
    unsigned cum1 = 0;
    if (fast){
        cum1 = s_above + s_hist[s_b];
        fast = (cum1 <= BUF);
    }
    unsigned b0f = s_b;
    __syncthreads();

    int cnt;
    if (fast){
        unsigned T = PREKEY + (b0f << 12);
        unsigned long long pthr = ((unsigned long long)T) << 17;
        int ccnt = (int)g_ccnt[n];
        if (ccnt > CAPI) ccnt = CAPI;
        for (int base = 0; base < ccnt; base += NT){
            int i = base + tid;
            unsigned long long e = (i < ccnt) ? cand[i] : 0ULL;
            bool take = (i < ccnt) && (e >= pthr);
            unsigned bal = __ballot_sync(0xffffffffu, take);
            if (bal){
                int ldr = __ffs(bal) - 1;
                int basep = 0;
                if (lane == ldr) basep = atomicAdd(&s_cnt, __popc(bal));
                basep = __shfl_sync(0xffffffffu, basep, ldr);
                if (take)
                    s_keys[basep + __popc(bal & ((1u << lane) - 1u))] = e;
            }
        }
        __syncthreads();
        cnt = s_cnt;
    } else {
        // ---- FALLBACK: full exact recompute + radix select (general data)
        const float* cls = gcls + (size_t)n * NENT;
        const float* ctrv = g_ctrv + (size_t)n * HW;
        unsigned* keys = g_keys + (size_t)n * NENT;
        if (tid == 0) s_tot2 = 0;
        for (int i = tid; i < 2048; i += NT) s_hist[i] = 0u;
        __syncthreads();
        int totL = 0;
        for (int i = tid; i < NENT; i += NT){
            int c = i / HW;
            int loc = i - c * HW;
            float sv = __fmul_rn(sig_x(cls[i]), ctrv[loc]);
            unsigned ok = __float_as_uint(sv) | 0x80000000u;
            keys[i] = ok;
            if (ok > KTH){ totL++; atomicAdd(&s_hist[(ok >> 15) & 0x7FFu], 1u); }
        }
        #pragma unroll
        for (int off = 16; off; off >>= 1) totL += __shfl_down_sync(0xffffffffu, totL, off);
        if (lane == 0) atomicAdd(&s_tot2, totL);
        if (tid == 0) s_b = 0xFFFFFFFFu;
        __syncthreads();
        int total = s_tot2;

        find_cross2048(s_hist, s_scan, TOPK, &s_b, &s_above, &s_total);
        int mode; unsigned T = 0; int needed = 0;
        if (total < TOPK){
            mode = 2; T = 0u; needed = TOPK - total;
        } else {
            unsigned b0 = s_b;
            unsigned above1 = s_above;
            unsigned c1 = above1 + s_hist[b0];
            __syncthreads();
            if (c1 <= BUF){
                mode = 0; T = TOPBITS | (b0 << 15);
            } else {
                for (int i = tid; i < 2048; i += NT) s_hist[i] = 0u;
                __syncthreads();
                for (int i = tid; i < NENT; i += NT){
                    unsigned ok = keys[i];
                    if (ok > KTH && ((ok >> 15) & 0x7FFu) == b0)
                        atomicAdd(&s_hist[(ok >> 4) & 0x7FFu], 1u);
                }
                __syncthreads();
                find_cross2048(s_hist, s_scan, TOPK - above1, &s_b, &s_above, &s_total);
                unsigned b1 = s_b;
                unsigned above2 = above1 + s_above;
                unsigned c2 = above2 + s_hist[b1];
                __syncthreads();
                if (c2 <= BUF){
                    mode = 0; T = TOPBITS | (b0 << 15) | (b1 << 4);
                } else {
                    if (tid < 16) s_hist[tid] = 0u;
                    __syncthreads();
                    unsigned winhi = (TOPBITS | (b0 << 15) | (b1 << 4)) >> 4;
                    for (int i = tid; i < NENT; i += NT){
                        unsigned ok = keys[i];
                        if (ok > KTH && (ok >> 4) == winhi)
                            atomicAdd(&s_hist[ok & 0xFu], 1u);
                    }
                    __syncthreads();
                    if (tid == 0){
                        unsigned K3 = TOPK - above2, run = 0;
                        for (int b = 15; b >= 0; b--){
                            unsigned h = s_hist[b];
                            if (run + h >= K3){ s_b = (unsigned)b; s_above = run; break; }
                            run += h;
                        }
                    }
                    __syncthreads();
                    unsigned b2 = s_b;
                    unsigned above3 = above2 + s_above;
                    unsigned c3 = above3 + s_hist[b2];
                    __syncthreads();
                    T = TOPBITS | (b0 << 15) | (b1 << 4) | b2;
                    if (c3 <= BUF) mode = 0;
                    else { mode = 1; needed = TOPK - (int)above3; }
                }
            }
        }
        for (int i = tid; i < NENT; i += NT){
            unsigned ok = keys[i];
            bool take = (ok > KTH) && (mode == 1 ? (ok > T) : (ok >= T));
            if (take){
                int c = i / HW;
                int loc = i - c * HW;
                int f = loc * NCLS + c;
                s_keys[atomicAdd(&s_cnt, 1)] = ((unsigned long long)ok << 17) | (unsigned)(NENT - f);
            }
        }
        __syncthreads();
        cnt = s_cnt;
        if (mode != 0){
            if (tid == 0) s_fill = 0;
            __syncthreads();
            unsigned fillHigh = (mode == 1) ? T : 0u;
            for (int fb = 0; fb < NENT; fb += NT){
                int f = fb + tid;
                bool eq = false;
                if (f < NENT){
                    int loc = f / NCLS;
                    int c = f - loc * NCLS;
                    unsigned ok = keys[c * HW + loc];
                    eq = (mode == 1) ? (ok == T) : (ok <= KTH);
                }
                unsigned bal = __ballot_sync(0xffffffffu, eq);
                if (lane == 0) s_wcnt[wrp] = (unsigned)__popc(bal);
                __syncthreads();
                if (tid == 0){
                    unsigned run = (unsigned)s_fill;
                    #pragma unroll
                    for (int i = 0; i < NT/32; i++){ s_woff[i] = run; run += s_wcnt[i]; }
                    s_fill = (int)run;
                }
                __syncthreads();
                if (eq){
                    int rank = (int)s_woff[wrp] + __popc(bal & ((1u << lane) - 1u));
                    if (rank < needed)
                        s_keys[cnt + rank] = ((unsigned long long)fillHigh << 17) | (unsigned)(NENT - f);
                }
                if (s_fill >= needed) break;
            }
            cnt = TOPK;
            __syncthreads();
        }
    }

    // ---- Prune to <= 1024 (rare)
    if (cnt > SRT){
        unsigned long long hi = 0;
        int K = TOPK, above = 0;
        unsigned long long thresholdP = 0;
        #pragma unroll 1
        for (int l = 0; l < 5; l++){
            const int sh = (l==0)?38:(l==1)?27:(l==2)?16:(l==3)?5:0;
            const int wb = (l==4)?5:11;
            for (int i = tid; i < 2048; i += NT) s_hist[i] = 0u;
            __syncthreads();
            for (int i = tid; i < cnt; i += NT){
                unsigned long long p = s_keys[i];
                if ((p >> (sh + wb)) == hi)
                    atomicAdd(&s_hist[(unsigned)((p >> sh) & ((1u << wb) - 1u))], 1u);
            }
            __syncthreads();
            find_cross2048(s_hist, s_scan, (unsigned)K, &s_b, &s_above, &s_total);
            unsigned b = s_b, aw = s_above, hb = s_hist[b];
            __syncthreads();
            if (above + (int)aw + (int)hb <= SRT){
                thresholdP = ((hi << wb) | b) << sh;
                break;
            }
            above += (int)aw; K -= (int)aw; hi = (hi << wb) | b;
        }
        for (int base = 0; base < cnt; base += NT){
            int i = base + tid;
            bool take = (i < cnt) && (s_keys[i] >= thresholdP);
            unsigned bal = __ballot_sync(0xffffffffu, take);
            if (bal){
                int ldr = __ffs(bal) - 1;
                int basep = 0;
                if (lane == ldr) basep = atomicAdd(&s_cnt2, __popc(bal));
                basep = __shfl_sync(0xffffffffu, basep, ldr);
                if (take)
                    s_out[basep + __popc(bal & ((1u << lane) - 1u))] = s_keys[i];
            }
        }
        __syncthreads();
        int c2 = s_cnt2;
        for (int i = tid; i < SRT; i += NT)
            if (i >= c2) s_out[i] = 0ULL;
    } else {
        for (int i = tid; i < SRT; i += NT)
            s_out[i] = (i < cnt) ? s_keys[i] : 0ULL;
    }
    __syncthreads();

    // ---- Bitonic sort, descending, 1024 u64
    for (unsigned k = 2; k <= SRT; k <<= 1){
        for (unsigned j = k >> 1; j > 0; j >>= 1){
            #pragma unroll
            for (int t = 0; t < SRT/NT; t++){
                int i = tid + t * NT;
                unsigned ixj = (unsigned)i ^ j;
                if (ixj > (unsigned)i){
                    unsigned long long a = s_out[i];
                    unsigned long long b = s_out[ixj];
                    bool desc = ((i & k) == 0);
                    if (desc ? (a < b) : (a > b)){
                        s_out[i] = b; s_out[ixj] = a;
                    }
                }
            }
            __syncthreads();
        }
    }

    // ---- Decode + write outputs (rounding-pinned; verified bit-exact)
    const size_t detB = 0;
    const size_t scB  = (size_t)NIMG * TOPK * 4;
    const size_t lbB  = scB + (size_t)NIMG * TOPK;
    const size_t vaB  = lbB + (size_t)NIMG * TOPK;
    const size_t hdB  = vaB + (size_t)NIMG * TOPK;
    const size_t hsB  = hdB + (size_t)NIMG * NCLS * 4;
    const float bx = gbox[n*4+0], by = gbox[n*4+1];
    const float sx = __fsub_rn(gbox[n*4+2], bx);
    const float sy = __fsub_rn(gbox[n*4+3], by);
    const float ps = gps[n];

    for (int i = tid; i < TOPK; i += NT){
        unsigned long long e = s_out[i];
        unsigned ok = (unsigned)(e >> 17);
        int f = NENT - (int)(e & 0x1FFFFu);
        int loc = f / NCLS;
        int c = f - loc * NCLS;
        int h = loc / RES, w = loc - h * RES;
        float lx = w + 0.5f, ly = h + 0.5f;
        float r0 = reg[loc], r1 = reg[HW + loc], r2 = reg[2*HW + loc], r3 = reg[3*HW + loc];
        float x1 = __fadd_rn(__fmul_rn(__fdiv_rn(__fsub_rn(lx, r0), 56.0f), sx), bx);
        float y1 = __fadd_rn(__fmul_rn(__fdiv_rn(__fsub_rn(ly, r1), 56.0f), sy), by);
        float x2 = __fadd_rn(__fmul_rn(__fdiv_rn(__fadd_rn(lx, r2), 56.0f), sx), bx);
        float y2 = __fadd_rn(__fmul_rn(__fdiv_rn(__fadd_rn(ly, r3), 56.0f), sy), by);
        x1 = fminf(fmaxf(x1, 0.0f), 1332.0f);
        x2 = fminf(fmaxf(x2, 0.0f), 1332.0f);
        y1 = fminf(fmaxf(y1, 0.0f),  799.0f);
        y2 = fminf(fmaxf(y2, 0.0f),  799.0f);
        bool valid = (ok > KTH) && (__fsub_rn(x2, x1) >= 0.0f) && (__fsub_rn(y2, y1) >= 0.0f);
        float val = __uint_as_float(ok ^ 0x80000000u);
        float sc = valid ? __fsqrt_rn(__fmul_rn(__fsqrt_rn(val), ps)) : 0.0f;
        size_t row = (size_t)n * TOPK + i;
        out[detB + row*4 + 0] = x1;
        out[detB + row*4 + 1] = y1;
        out[detB + row*4 + 2] = x2;
        out[detB + row*4 + 3] = y2;
        out[scB + row] = sc;
        out[lbB + row] = (float)(c + 2);
        out[vaB + row] = valid ? 1.0f : 0.0f;
    }

    if (tid < NCLS){
        unsigned long long e = g_cls[(size_t)n * NCLS + tid];
        unsigned ok = (unsigned)(e >> 32);
        int loc = HW - 1 - (int)(e & 0xFFFFFFFFu);
        int h = loc / RES, w = loc - h * RES;
        float lx = w + 0.5f, ly = h + 0.5f;
        float r0 = reg[loc], r1 = reg[HW + loc], r2 = reg[2*HW + loc], r3 = reg[3*HW + loc];
        float x1 = __fadd_rn(__fmul_rn(__fdiv_rn(__fsub_rn(lx, r0), 56.0f), sx), bx);
        float y1 = __fadd_rn(__fmul_rn(__fdiv_rn(__fsub_rn(ly, r1), 56.0f), sy), by);
        float x2 = __fadd_rn(__fmul_rn(__fdiv_rn(__fadd_rn(lx, r2), 56.0f), sx), bx);
        float y2 = __fadd_rn(__fmul_rn(__fdiv_rn(__fadd_rn(ly, r3), 56.0f), sy), by);
        float hv = __uint_as_float(ok ^ 0x80000000u);
        float hs = (hv >= 0.9f) ? __fsqrt_rn(__fmul_rn(__fsqrt_rn(hv), ps)) : 0.0f;
        size_t rr = (size_t)n * NCLS + tid;
        out[hdB + rr*4 + 0] = x1;
        out[hdB + rr*4 + 1] = y1;
        out[hdB + rr*4 + 2] = x2;
        out[hdB + rr*4 + 3] = y2;
        out[hsB + rr] = hs;
    }
}

extern "C" void kernel_launch(void* const* d_in, const int* in_sizes, int n_in,
                              void* d_out, int out_size)
{
    const float *bcls = nullptr, *breg = nullptr, *bctr = nullptr,
                *bbox = nullptr, *bps = nullptr;
    for (int i = 0; i < n_in; i++){
        switch (in_sizes[i]){
            case 32112640: bcls = (const float*)d_in[i]; break;
            case 6422528:  breg = (const float*)d_in[i]; break;
            case 1605632:  bctr = (const float*)d_in[i]; break;
            case 2048:     bbox = (const float*)d_in[i]; break;
            case 512:      bps  = (const float*)d_in[i]; break;
            default: break;
        }
    }
    (void)out_size;
    k0_ctr<<<NIMG, NT>>>(bctr);
    k1_keys<<<dim3(NPART, NIMG), NT>>>(bcls);
    k2_select<<<NIMG, NT>>>(bcls, breg, bbox, bps, (float*)d_out);
}

// round 13
// speedup vs baseline: 1.0961x; 1.0320x over previous
#include <cuda_runtime.h>
#include <math_constants.h>

#define NIMG 512
#define NCLS 20
#define RES 56
#define HW 3136            // 56*56
#define HWF4 (HW/4)        // 784
#define NENT 62720         // HW*NCLS
#define NPART 5
#define CPP 4              // classes per k1 CTA
#define TOPK 1000
#define BUF 2048
#define SRT 1024
#define NT 512
#define CAPI 12288         // per-image candidate capacity (mean ~5.7K)
#define KTH     0xBD4CCCCDu   // key(0.05f)
#define PREKEY  0xBF000000u   // key(0.5f) exact pre-filter for selection
#define KEY046  0xBEEB851Fu   // key(0.46f) argmax fallback guard
#define TOPBITS 0xBC000000u

__device__ float    g_ctrv[(size_t)NIMG * HW];
__device__ float    g_xcut[(size_t)NIMG * HW];   // logit(0.449/ctr) screen cutoff
__device__ unsigned long long g_cand[(size_t)NIMG * CAPI];
__device__ unsigned g_ccnt[NIMG];
__device__ unsigned g_ovf[NIMG];
__device__ unsigned g_keys[(size_t)NIMG * NENT];   // FALLBACK ONLY

// Faithful replica of XLA:CPU's vectorized exp (Cephes/Eigen pexp<float>),
// UNFUSED mul/add rounding. DO NOT TOUCH — bit-exactness verified.
__device__ __forceinline__ float cephes_expf(float x){
    const float exp_hi = 88.3762626647950f;
    const float exp_lo = -88.3762626647949f;
    const float LOG2EF = 1.44269504088896341f;
    const float C1 = 0.693359375f;
    const float C2 = -2.12194440e-4f;
    float xc = fminf(fmaxf(x, exp_lo), exp_hi);
    float m = floorf(__fadd_rn(__fmul_rn(xc, LOG2EF), 0.5f));
    float r = __fsub_rn(xc, __fmul_rn(m, C1));
    r = __fsub_rn(r, __fmul_rn(m, C2));
    float r2 = __fmul_rn(r, r);
    float y = 1.9875691500e-4f;
    y = __fadd_rn(__fmul_rn(y, r), 1.3981999507e-3f);
    y = __fadd_rn(__fmul_rn(y, r), 8.3334519073e-3f);
    y = __fadd_rn(__fmul_rn(y, r), 4.1665795894e-2f);
    y = __fadd_rn(__fmul_rn(y, r), 1.6666665459e-1f);
    y = __fadd_rn(__fmul_rn(y, r), 5.0000001201e-1f);
    y = __fadd_rn(__fmul_rn(y, r2), r);
    y = __fadd_rn(y, 1.0f);
    int mi = (int)m;
    float sc = __int_as_float((mi + 127) << 23);
    return __fmul_rn(y, sc);
}

__device__ __forceinline__ float sig_x(float x){
    float e = cephes_expf(-x);
    return __fdiv_rn(1.0f, __fadd_rn(1.0f, e));
}

// Screen cutoff: x > xcut(c) <=> sigmoid(x)*c > ~0.449 (conservative; approx ok).
__device__ __forceinline__ float xcut_of(float c){
    float ratio = 0.449f / c;
    if (!(ratio < 1.0f)) return CUDART_INF_F;
    return __logf(ratio / (1.0f - ratio));
}

// ============== Kernel 0: exact ctr sigmoids + screen cutoffs + init ==============
__global__ void __launch_bounds__(NT)
k0_ctr(const float* __restrict__ gctr)
{
    const int n = blockIdx.x;
    const float4* src = (const float4*)(gctr + (size_t)n * HW);
    float4* dst = (float4*)(g_ctrv + (size_t)n * HW);
    float4* xct = (float4*)(g_xcut + (size_t)n * HW);
    for (int i4 = threadIdx.x; i4 < HWF4; i4 += NT){
        float4 v = src[i4];
        float4 r;
        r.x = sig_x(v.x); r.y = sig_x(v.y);
        r.z = sig_x(v.z); r.w = sig_x(v.w);
        dst[i4] = r;
        float4 t;
        t.x = xcut_of(r.x); t.y = xcut_of(r.y);
        t.z = xcut_of(r.z); t.w = xcut_of(r.w);
        xct[i4] = t;
    }
    if (threadIdx.x == 0){ g_ccnt[n] = 0u; g_ovf[n] = 0u; }
}

// ============== Kernel 1: PURE streaming screen (no smem, no tail work) ==============
__global__ void __launch_bounds__(NT, 2)
k1_screen(const float* __restrict__ gcls)
{
    const int part = blockIdx.x;
    const int n    = blockIdx.y;
    const int tid  = threadIdx.x;
    const int lane = tid & 31;
    const float4* colBase = (const float4*)(gcls + (size_t)n * NENT + part * (CPP * HW));
    const float4* xct4 = (const float4*)(g_xcut + (size_t)n * HW);

    // Burst: 10 independent LDG.128 per thread
    float4 xc[2], d[2][CPP];
    #pragma unroll
    for (int w = 0; w < 2; w++){
        int lc = tid + w * NT;
        bool ib = (lc < HWF4);
        xc[w] = ib ? xct4[lc] : make_float4(CUDART_INF_F, CUDART_INF_F,
                                            CUDART_INF_F, CUDART_INF_F);
        #pragma unroll
        for (int c = 0; c < CPP; c++)
            d[w][c] = ib ? colBase[c * HWF4 + lc]
                         : make_float4(-1e9f, -1e9f, -1e9f, -1e9f);
    }
    unsigned hm = 0;
    #pragma unroll
    for (int w = 0; w < 2; w++){
        #pragma unroll
        for (int c = 0; c < CPP; c++){
            #pragma unroll
            for (int j = 0; j < 4; j++){
                float x  = j==0 ? d[w][c].x : j==1 ? d[w][c].y : j==2 ? d[w][c].z : d[w][c].w;
                float cu = j==0 ? xc[w].x   : j==1 ? xc[w].y   : j==2 ? xc[w].z   : xc[w].w;
                if (x > cu) hm |= 1u << (w * 16 + c * 4 + j);
            }
        }
    }
    unsigned h = (unsigned)__popc(hm);
    unsigned incl = h;
    #pragma unroll
    for (int off = 1; off < 32; off <<= 1){
        unsigned t = __shfl_up_sync(0xffffffffu, incl, off);
        if (lane >= off) incl += t;
    }
    unsigned wtot = __shfl_sync(0xffffffffu, incl, 31);
    unsigned wbase = 0;
    if (wtot){
        if (lane == 31) wbase = atomicAdd(&g_ccnt[n], wtot);
        wbase = __shfl_sync(0xffffffffu, wbase, 31);
    }
    unsigned p = wbase + incl - h;
    if (hm){
        unsigned long long* cand = g_cand + (size_t)n * CAPI;
        const int pbase = part * (CPP * HW);
        bool clip = false;
        #pragma unroll
        for (int w = 0; w < 2; w++){
            #pragma unroll
            for (int c = 0; c < CPP; c++){
                #pragma unroll
                for (int j = 0; j < 4; j++){
                    if (hm & (1u << (w * 16 + c * 4 + j))){
                        float x = j==0 ? d[w][c].x : j==1 ? d[w][c].y : j==2 ? d[w][c].z : d[w][c].w;
                        if (p < CAPI){
                            unsigned idx = (unsigned)(pbase + c * HW + 4 * (tid + w * NT) + j);
                            cand[p] = ((unsigned long long)idx << 32)
                                    | (unsigned long long)__float_as_uint(x);
                        } else clip = true;
                        p++;
                    }
                }
            }
        }
        if (clip) g_ovf[n] = 1u;
    }
}

// ============== shared helper ==============
__device__ void find_cross2048(unsigned* s_hist, unsigned* s_scan, unsigned K,
                               unsigned* s_b, unsigned* s_above, unsigned* s_total)
{
    const int tid = threadIdx.x;
    const int top = 2047 - tid * 4;
    unsigned part = 0;
    #pragma unroll
    for (int j = 0; j < 4; j++) part += s_hist[top - j];
    s_scan[tid] = part;
    __syncthreads();
    for (int off = 1; off < NT; off <<= 1){
        unsigned v = (tid >= off) ? s_scan[tid - off] : 0u;
        __syncthreads();
        s_scan[tid] += v;
        __syncthreads();
    }
    unsigned incl = s_scan[tid];
    unsigned excl = incl - part;
    if (tid == NT - 1) *s_total = incl;
    if (excl < K && incl >= K){
        unsigned run = excl;
        #pragma unroll
        for (int j = 0; j < 4; j++){
            int b = top - j;
            unsigned h = s_hist[b];
            if (run + h >= K){ *s_b = (unsigned)b; *s_above = run; break; }
            run += h;
        }
    }
    __syncthreads();
}

// ============== Kernel 2: exact eval + threshold + filter + sort + decode ==============
__global__ void __launch_bounds__(NT)
k2_select(const float* __restrict__ gcls, const float* __restrict__ greg,
          const float* __restrict__ gbox, const float* __restrict__ gps,
          float* __restrict__ out)
{
    __shared__ unsigned s_hist[2048];
    __shared__ unsigned s_scan[NT];
    __shared__ unsigned long long s_keys[BUF];
    __shared__ unsigned long long s_out[SRT];
    __shared__ unsigned long long s_cls[NCLS];
    __shared__ unsigned s_b, s_above, s_total;
    __shared__ int s_cnt, s_cnt2, s_fill, s_tot2;
    __shared__ unsigned s_wcnt[NT/32], s_woff[NT/32];

    const int n    = blockIdx.x;
    const int tid  = threadIdx.x;
    const int lane = tid & 31;
    const int wrp  = tid >> 5;
    const float* reg = greg + (size_t)n * 4 * HW;
    const float* ctrv = g_ctrv + (size_t)n * HW;
    unsigned long long* cand = g_cand + (size_t)n * CAPI;

    for (int i = tid; i < 2048; i += NT) s_hist[i] = 0u;
    if (tid < NCLS) s_cls[tid] = 0ULL;
    if (tid == 0){ s_b = 0xFFFFFFFFu; s_cnt = 0; s_cnt2 = 0; }
    __syncthreads();

    const bool ovf = (g_ovf[n] != 0u);
    int ccnt = (int)g_ccnt[n];
    if (ccnt > CAPI) ccnt = CAPI;

    // ---- Exact evaluation of screen candidates: hist + class max + packed write-back
    for (int i = tid; i < ccnt; i += NT){
        unsigned long long e = cand[i];
        int idx = (int)(e >> 32);
        float x = __uint_as_float((unsigned)e);
        int cg = idx / HW;
        int loc = idx - cg * HW;
        float sv = __fmul_rn(sig_x(x), ctrv[loc]);
        unsigned key = __float_as_uint(sv) | 0x80000000u;
        unsigned long long pk = ((unsigned long long)key << 32) | (unsigned)(HW - 1 - loc);
        if (pk > *((volatile unsigned long long*)&s_cls[cg]))
            atomicMax(&s_cls[cg], pk);
        unsigned long long packed = 0ULL;
        if (key >= PREKEY){
            unsigned bin = (key - PREKEY) >> 12;
            if (bin > 2047u) bin = 2047u;
            atomicAdd(&s_hist[bin], 1u);
            int f = loc * NCLS + cg;
            packed = ((unsigned long long)key << 17) | (unsigned)(NENT - f);
        }
        cand[i] = packed;
    }
    __syncthreads();

    // ---- Per-class guarded dense fallback (exact max < 0.46 among cands, or ovf)
    for (int cg = 0; cg < NCLS; cg++){
        bool need = ovf || ((unsigned)(s_cls[cg] >> 32) < KEY046);
        if (need){
            const float* colp = gcls + (size_t)n * NENT + cg * HW;
            unsigned long long best = 0ULL;
            for (int loc = tid; loc < HW; loc += NT){
                float sv = __fmul_rn(sig_x(colp[loc]), ctrv[loc]);
                unsigned key = __float_as_uint(sv) | 0x80000000u;
                unsigned long long pk = ((unsigned long long)key << 32) | (unsigned)(HW - 1 - loc);
                if (pk > best) best = pk;
            }
            #pragma unroll
            for (int off = 16; off; off >>= 1){
                unsigned long long o = __shfl_down_sync(0xffffffffu, best, off);
                if (o > best) best = o;
            }
            if (lane == 0) atomicMax(&s_cls[cg], best);
        }
    }
    __syncthreads();

    // ---- Threshold
    find_cross2048(s_hist, s_scan, TOPK, &s_b, &s_above, &s_total);
    bool fast = (s_b != 0xFFFFFFFFu) && !ovf;
    if (fast) fast = (s_above + s_hist[s_b] <= BUF);
    unsigned b0f = s_b;
    __syncthreads();

    int cnt;
    if (fast){
        unsigned long long pthr = ((unsigned long long)(PREKEY + (b0f << 12))) << 17;
        for (int base = 0; base < ccnt; base += NT){
            int i = base + tid;
            unsigned long long e = (i < ccnt) ? cand[i] : 0ULL;
            bool take = (e >= pthr);
            unsigned bal = __ballot_sync(0xffffffffu, take);
            if (bal){
                int ldr = __ffs(bal) - 1;
                int basep = 0;
                if (lane == ldr) basep = atomicAdd(&s_cnt, __popc(bal));
                basep = __shfl_sync(0xffffffffu, basep, ldr);
                if (take)
                    s_keys[basep + __popc(bal & ((1u << lane) - 1u))] = e;
            }
        }
        __syncthreads();
        cnt = s_cnt;
    } else {
        // ---- FALLBACK: full exact recompute + radix select (general data)
        const float* cls = gcls + (size_t)n * NENT;
        unsigned* keys = g_keys + (size_t)n * NENT;
        if (tid == 0) s_tot2 = 0;
        for (int i = tid; i < 2048; i += NT) s_hist[i] = 0u;
        __syncthreads();
        int totL = 0;
        for (int i = tid; i < NENT; i += NT){
            int c = i / HW;
            int loc = i - c * HW;
            float sv = __fmul_rn(sig_x(cls[i]), ctrv[loc]);
            unsigned ok = __float_as_uint(sv) | 0x80000000u;
            keys[i] = ok;
            if (ok > KTH){ totL++; atomicAdd(&s_hist[(ok >> 15) & 0x7FFu], 1u); }
        }
        #pragma unroll
        for (int off = 16; off; off >>= 1) totL += __shfl_down_sync(0xffffffffu, totL, off);
        if (lane == 0) atomicAdd(&s_tot2, totL);
        if (tid == 0) s_b = 0xFFFFFFFFu;
        __syncthreads();
        int total = s_tot2;

        find_cross2048(s_hist, s_scan, TOPK, &s_b, &s_above, &s_total);
        int mode; unsigned T = 0; int needed = 0;
        if (total < TOPK){
            mode = 2; T = 0u; needed = TOPK - total;
        } else {
            unsigned b0 = s_b;
            unsigned above1 = s_above;
            unsigned c1 = above1 + s_hist[b0];
            __syncthreads();
            if (c1 <= BUF){
                mode = 0; T = TOPBITS | (b0 << 15);
            } else {
                for (int i = tid; i < 2048; i += NT) s_hist[i] = 0u;
                __syncthreads();
                for (int i = tid; i < NENT; i += NT){
                    unsigned ok = keys[i];
                    if (ok > KTH && ((ok >> 15) & 0x7FFu) == b0)
                        atomicAdd(&s_hist[(ok >> 4) & 0x7FFu], 1u);
                }
                __syncthreads();
                find_cross2048(s_hist, s_scan, TOPK - above1, &s_b, &s_above, &s_total);
                unsigned b1 = s_b;
                unsigned above2 = above1 + s_above;
                unsigned c2 = above2 + s_hist[b1];
                __syncthreads();
                if (c2 <= BUF){
                    mode = 0; T = TOPBITS | (b0 << 15) | (b1 << 4);
                } else {
                    if (tid < 16) s_hist[tid] = 0u;
                    __syncthreads();
                    unsigned winhi = (TOPBITS | (b0 << 15) | (b1 << 4)) >> 4;
                    for (int i = tid; i < NENT; i += NT){
                        unsigned ok = keys[i];
                        if (ok > KTH && (ok >> 4) == winhi)
                            atomicAdd(&s_hist[ok & 0xFu], 1u);
                    }
                    __syncthreads();
                    if (tid == 0){
                        unsigned K3 = TOPK - above2, run = 0;
                        for (int b = 15; b >= 0; b--){
                            unsigned h = s_hist[b];
                            if (run + h >= K3){ s_b = (unsigned)b; s_above = run; break; }
                            run += h;
                        }
                    }
                    __syncthreads();
                    unsigned b2 = s_b;
                    unsigned above3 = above2 + s_above;
                    unsigned c3 = above3 + s_hist[b2];
                    __syncthreads();
                    T = TOPBITS | (b0 << 15) | (b1 << 4) | b2;
                    if (c3 <= BUF) mode = 0;
                    else { mode = 1; needed = TOPK - (int)above3; }
                }
            }
        }
        for (int i = tid; i < NENT; i += NT){
            unsigned ok = keys[i];
            bool take = (ok > KTH) && (mode == 1 ? (ok > T) : (ok >= T));
            if (take){
                int c = i / HW;
                int loc = i - c * HW;
                int f = loc * NCLS + c;
                s_keys[atomicAdd(&s_cnt, 1)] = ((unsigned long long)ok << 17) | (unsigned)(NENT - f);
            }
        }
        __syncthreads();
        cnt = s_cnt;
        if (mode != 0){
            if (tid == 0) s_fill = 0;
            __syncthreads();
            unsigned fillHigh = (mode == 1) ? T : 0u;
            for (int fb = 0; fb < NENT; fb += NT){
                int f = fb + tid;
                bool eq = false;
                if (f < NENT){
                    int loc = f / NCLS;
                    int c = f - loc * NCLS;
                    unsigned ok = keys[c * HW + loc];
                    eq = (mode == 1) ? (ok == T) : (ok <= KTH);
                }
                unsigned bal = __ballot_sync(0xffffffffu, eq);
                if (lane == 0) s_wcnt[wrp] = (unsigned)__popc(bal);
                __syncthreads();
                if (tid == 0){
                    unsigned run = (unsigned)s_fill;
                    #pragma unroll
                    for (int i = 0; i < NT/32; i++){ s_woff[i] = run; run += s_wcnt[i]; }
                    s_fill = (int)run;
                }
                __syncthreads();
                if (eq){
                    int rank = (int)s_woff[wrp] + __popc(bal & ((1u << lane) - 1u));
                    if (rank < needed)
                        s_keys[cnt + rank] = ((unsigned long long)fillHigh << 17) | (unsigned)(NENT - f);
                }
                if (s_fill >= needed) break;
            }
            cnt = TOPK;
            __syncthreads();
        }
    }

    // ---- Prune to <= 1024 (rare)
    if (cnt > SRT){
        unsigned long long hi = 0;
        int K = TOPK, above = 0;
        unsigned long long thresholdP = 0;
        #pragma unroll 1
        for (int l = 0; l < 5; l++){
            const int sh = (l==0)?38:(l==1)?27:(l==2)?16:(l==3)?5:0;
            const int wb = (l==4)?5:11;
            for (int i = tid; i < 2048; i += NT) s_hist[i] = 0u;
            __syncthreads();
            for (int i = tid; i < cnt; i += NT){
                unsigned long long p = s_keys[i];
                if ((p >> (sh + wb)) == hi)
                    atomicAdd(&s_hist[(unsigned)((p >> sh) & ((1u << wb) - 1u))], 1u);
            }
            __syncthreads();
            find_cross2048(s_hist, s_scan, (unsigned)K, &s_b, &s_above, &s_total);
            unsigned b = s_b, aw = s_above, hb = s_hist[b];
            __syncthreads();
            if (above + (int)aw + (int)hb <= SRT){
                thresholdP = ((hi << wb) | b) << sh;
                break;
            }
            above += (int)aw; K -= (int)aw; hi = (hi << wb) | b;
        }
        for (int base = 0; base < cnt; base += NT){
            int i = base + tid;
            bool take = (i < cnt) && (s_keys[i] >= thresholdP);
            unsigned bal = __ballot_sync(0xffffffffu, take);
            if (bal){
                int ldr = __ffs(bal) - 1;
                int basep = 0;
                if (lane == ldr) basep = atomicAdd(&s_cnt2, __popc(bal));
                basep = __shfl_sync(0xffffffffu, basep, ldr);
                if (take)
                    s_out[basep + __popc(bal & ((1u << lane) - 1u))] = s_keys[i];
            }
        }
        __syncthreads();
        int c2 = s_cnt2;
        for (int i = tid; i < SRT; i += NT)
            if (i >= c2) s_out[i] = 0ULL;
    } else {
        for (int i = tid; i < SRT; i += NT)
            s_out[i] = (i < cnt) ? s_keys[i] : 0ULL;
    }
    __syncthreads();

    // ---- Bitonic sort, descending, 1024 u64
    for (unsigned k = 2; k <= SRT; k <<= 1){
        for (unsigned j = k >> 1; j > 0; j >>= 1){
            #pragma unroll
            for (int t = 0; t < SRT/NT; t++){
                int i = tid + t * NT;
                unsigned ixj = (unsigned)i ^ j;
                if (ixj > (unsigned)i){
                    unsigned long long a = s_out[i];
                    unsigned long long b = s_out[ixj];
                    bool desc = ((i & k) == 0);
                    if (desc ? (a < b) : (a > b)){
                        s_out[i] = b; s_out[ixj] = a;
                    }
                }
            }
            __syncthreads();
        }
    }

    // ---- Decode + write outputs (rounding-pinned; verified bit-exact)
    const size_t detB = 0;
    const size_t scB  = (size_t)NIMG * TOPK * 4;
    const size_t lbB  = scB + (size_t)NIMG * TOPK;
    const size_t vaB  = lbB + (size_t)NIMG * TOPK;
    const size_t hdB  = vaB + (size_t)NIMG * TOPK;
    const size_t hsB  = hdB + (size_t)NIMG * NCLS * 4;
    const float bx = gbox[n*4+0], by = gbox[n*4+1];
    const float sx = __fsub_rn(gbox[n*4+2], bx);
    const float sy = __fsub_rn(gbox[n*4+3], by);
    const float ps = gps[n];

    for (int i = tid; i < TOPK; i += NT){
        unsigned long long e = s_out[i];
        unsigned ok = (unsigned)(e >> 17);
        int f = NENT - (int)(e & 0x1FFFFu);
        int loc = f / NCLS;
        int c = f - loc * NCLS;
        int h = loc / RES, w = loc - h * RES;
        float lx = w + 0.5f, ly = h + 0.5f;
        float r0 = reg[loc], r1 = reg[HW + loc], r2 = reg[2*HW + loc], r3 = reg[3*HW + loc];
        float x1 = __fadd_rn(__fmul_rn(__fdiv_rn(__fsub_rn(lx, r0), 56.0f), sx), bx);
        float y1 = __fadd_rn(__fmul_rn(__fdiv_rn(__fsub_rn(ly, r1), 56.0f), sy), by);
        float x2 = __fadd_rn(__fmul_rn(__fdiv_rn(__fadd_rn(lx, r2), 56.0f), sx), bx);
        float y2 = __fadd_rn(__fmul_rn(__fdiv_rn(__fadd_rn(ly, r3), 56.0f), sy), by);
        x1 = fminf(fmaxf(x1, 0.0f), 1332.0f);
        x2 = fminf(fmaxf(x2, 0.0f), 1332.0f);
        y1 = fminf(fmaxf(y1, 0.0f),  799.0f);
        y2 = fminf(fmaxf(y2, 0.0f),  799.0f);
        bool valid = (ok > KTH) && (__fsub_rn(x2, x1) >= 0.0f) && (__fsub_rn(y2, y1) >= 0.0f);
        float val = __uint_as_float(ok ^ 0x80000000u);
        float sc = valid ? __fsqrt_rn(__fmul_rn(__fsqrt_rn(val), ps)) : 0.0f;
        size_t row = (size_t)n * TOPK + i;
        out[detB + row*4 + 0] = x1;
        out[detB + row*4 + 1] = y1;
        out[detB + row*4 + 2] = x2;
        out[detB + row*4 + 3] = y2;
        out[scB + row] = sc;
        out[lbB + row] = (float)(c + 2);
        out[vaB + row] = valid ? 1.0f : 0.0f;
    }

    if (tid < NCLS){
        unsigned long long e = s_cls[tid];
        unsigned ok = (unsigned)(e >> 32);
        int loc = HW - 1 - (int)(e & 0xFFFFFFFFu);
        int h = loc / RES, w = loc - h * RES;
        float lx = w + 0.5f, ly = h + 0.5f;
        float r0 = reg[loc], r1 = reg[HW + loc], r2 = reg[2*HW + loc], r3 = reg[3*HW + loc];
        float x1 = __fadd_rn(__fmul_rn(__fdiv_rn(__fsub_rn(lx, r0), 56.0f), sx), bx);
        float y1 = __fadd_rn(__fmul_rn(__fdiv_rn(__fsub_rn(ly, r1), 56.0f), sy), by);
        float x2 = __fadd_rn(__fmul_rn(__fdiv_rn(__fadd_rn(lx, r2), 56.0f), sx), bx);
        float y2 = __fadd_rn(__fmul_rn(__fdiv_rn(__fadd_rn(ly, r3), 56.0f), sy), by);
        float hv = __uint_as_float(ok ^ 0x80000000u);
        float hs = (hv >= 0.9f) ? __fsqrt_rn(__fmul_rn(__fsqrt_rn(hv), ps)) : 0.0f;
        size_t rr = (size_t)n * NCLS + tid;
        out[hdB + rr*4 + 0] = x1;
        out[hdB + rr*4 + 1] = y1;
        out[hdB + rr*4 + 2] = x2;
        out[hdB + rr*4 + 3] = y2;
        out[hsB + rr] = hs;
    }
}

extern "C" void kernel_launch(void* const* d_in, const int* in_sizes, int n_in,
                              void* d_out, int out_size)
{
    const float *bcls = nullptr, *breg = nullptr, *bctr = nullptr,
                *bbox = nullptr, *bps = nullptr;
    for (int i = 0; i < n_in; i++){
        switch (in_sizes[i]){
            case 32112640: bcls = (const float*)d_in[i]; break;
            case 6422528:  breg = (const float*)d_in[i]; break;
            case 1605632:  bctr = (const float*)d_in[i]; break;
            case 2048:     bbox = (const float*)d_in[i]; break;
            case 512:      bps  = (const float*)d_in[i]; break;
            default: break;
        }
    }
    (void)out_size;
    k0_ctr<<<NIMG, NT>>>(bctr);
    k1_screen<<<dim3(NPART, NIMG), NT>>>(bcls);
    k2_select<<<NIMG, NT>>>(bcls, breg, bbox, bps, (float*)d_out);
}

// round 14
// speedup vs baseline: 1.2483x; 1.1389x over previous
#include <cuda_runtime.h>
#include <math_constants.h>

#define NIMG 512
#define NCLS 20
#define RES 56
#define HW 3136            // 56*56
#define HWF4 (HW/4)        // 784
#define NENT 62720         // HW*NCLS
#define NF4 (NENT/4)       // 15680
#define TOPK 1000
#define BUF 2048
#define SRT 1024
#define NT 512
#define CAPL 8192          // smem candidate list (mean ~5.7K)
#define KTH     0xBD4CCCCDu   // key(0.05f)
#define PREKEY  0xBF000000u   // key(0.5f) exact pre-filter for selection
#define KEY046  0xBEEB851Fu   // key(0.46f) argmax fallback guard
#define TOPBITS 0xBC000000u

// Dynamic smem layout (bytes):
//   keys   u64[2048]   @ 0       16384
//   cls    u64[24]     @ 16384     192
//   ctr    f32[3136]   @ 16576   12544
//   xcut   f32[3136]   @ 29120   12544
//   cand   u32[8192]   @ 41664   32768   (overlaid by srt u64[1024] after pass 2)
//   hist   u32[2048]   @ 74432    8192
//   scan   u32[512]    @ 82624    2048
// total 84672 B
#define SMEM_TOTAL 84672

__device__ unsigned g_keys[(size_t)NIMG * NENT];   // FALLBACK ONLY

// Faithful replica of XLA:CPU's vectorized exp (Cephes/Eigen pexp<float>),
// UNFUSED mul/add rounding. DO NOT TOUCH — bit-exactness verified.
__device__ __forceinline__ float cephes_expf(float x){
    const float exp_hi = 88.3762626647950f;
    const float exp_lo = -88.3762626647949f;
    const float LOG2EF = 1.44269504088896341f;
    const float C1 = 0.693359375f;
    const float C2 = -2.12194440e-4f;
    float xc = fminf(fmaxf(x, exp_lo), exp_hi);
    float m = floorf(__fadd_rn(__fmul_rn(xc, LOG2EF), 0.5f));
    float r = __fsub_rn(xc, __fmul_rn(m, C1));
    r = __fsub_rn(r, __fmul_rn(m, C2));
    float r2 = __fmul_rn(r, r);
    float y = 1.9875691500e-4f;
    y = __fadd_rn(__fmul_rn(y, r), 1.3981999507e-3f);
    y = __fadd_rn(__fmul_rn(y, r), 8.3334519073e-3f);
    y = __fadd_rn(__fmul_rn(y, r), 4.1665795894e-2f);
    y = __fadd_rn(__fmul_rn(y, r), 1.6666665459e-1f);
    y = __fadd_rn(__fmul_rn(y, r), 5.0000001201e-1f);
    y = __fadd_rn(__fmul_rn(y, r2), r);
    y = __fadd_rn(y, 1.0f);
    int mi = (int)m;
    float sc = __int_as_float((mi + 127) << 23);
    return __fmul_rn(y, sc);
}

__device__ __forceinline__ float sig_x(float x){
    float e = cephes_expf(-x);
    return __fdiv_rn(1.0f, __fadd_rn(1.0f, e));
}

// Screen cutoff: x > xcut(c) <=> sigmoid(x)*c > ~0.449 (conservative; approx ok).
__device__ __forceinline__ float xcut_of(float c){
    float ratio = 0.449f / c;
    if (!(ratio < 1.0f)) return CUDART_INF_F;
    return __logf(ratio / (1.0f - ratio));
}

__device__ void find_cross2048(unsigned* s_hist, unsigned* s_scan, unsigned K,
                               unsigned* s_b, unsigned* s_above, unsigned* s_total)
{
    const int tid = threadIdx.x;
    const int top = 2047 - tid * 4;
    unsigned part = 0;
    #pragma unroll
    for (int j = 0; j < 4; j++) part += s_hist[top - j];
    s_scan[tid] = part;
    __syncthreads();
    for (int off = 1; off < NT; off <<= 1){
        unsigned v = (tid >= off) ? s_scan[tid - off] : 0u;
        __syncthreads();
        s_scan[tid] += v;
        __syncthreads();
    }
    unsigned incl = s_scan[tid];
    unsigned excl = incl - part;
    if (tid == NT - 1) *s_total = incl;
    if (excl < K && incl >= K){
        unsigned run = excl;
        #pragma unroll
        for (int j = 0; j < 4; j++){
            int b = top - j;
            unsigned h = s_hist[b];
            if (run + h >= K){ *s_b = (unsigned)b; *s_above = run; break; }
            run += h;
        }
    }
    __syncthreads();
}

// ============== Fused kernel: one CTA per image ==============
__global__ void __launch_bounds__(NT, 2)
post_fused(const float* __restrict__ gcls, const float* __restrict__ greg,
           const float* __restrict__ gctr, const float* __restrict__ gbox,
           const float* __restrict__ gps, float* __restrict__ out)
{
    extern __shared__ unsigned char dyn[];
    unsigned long long* s_keys = (unsigned long long*)(dyn);
    unsigned long long* s_cls  = (unsigned long long*)(dyn + 16384);
    float*    s_ctr  = (float*)(dyn + 16576);
    float*    s_xcut = (float*)(dyn + 29120);
    unsigned* s_cand = (unsigned*)(dyn + 41664);
    unsigned long long* s_srt = (unsigned long long*)(dyn + 41664);  // overlay
    unsigned* s_hist = (unsigned*)(dyn + 74432);
    unsigned* s_scan = (unsigned*)(dyn + 82624);

    __shared__ unsigned s_nc, s_b, s_above, s_total;
    __shared__ int s_cnt, s_cnt2, s_fill, s_tot2;
    __shared__ unsigned s_wcnt[NT/32], s_woff[NT/32];

    const int n    = blockIdx.x;
    const int tid  = threadIdx.x;
    const int lane = tid & 31;
    const int wrp  = tid >> 5;
    const float* cls = gcls + (size_t)n * NENT;
    const float* reg = greg + (size_t)n * 4 * HW;

    // ---- Phase 0: ctr sigmoids + screen cutoffs into smem
    {
        const float4* src = (const float4*)(gctr + (size_t)n * HW);
        for (int i4 = tid; i4 < HWF4; i4 += NT){
            float4 v = src[i4];
            float4 r;
            r.x = sig_x(v.x); r.y = sig_x(v.y);
            r.z = sig_x(v.z); r.w = sig_x(v.w);
            ((float4*)s_ctr)[i4] = r;
            float4 t;
            t.x = xcut_of(r.x); t.y = xcut_of(r.y);
            t.z = xcut_of(r.z); t.w = xcut_of(r.w);
            ((float4*)s_xcut)[i4] = t;
        }
    }
    for (int i = tid; i < 2048; i += NT) s_hist[i] = 0u;
    if (tid < NCLS) s_cls[tid] = 0ULL;
    if (tid == 0){ s_nc = 0u; s_cnt = 0; s_cnt2 = 0; s_b = 0xFFFFFFFFu; }
    __syncthreads();

    // ---- Phase 1: stream box_cls, screen, append u32 indices to s_cand
    const float4* colBase = (const float4*)cls;
    #pragma unroll 1
    for (int it = 0; it < 4; it++){
        const int base = it * 8 * NT;
        float4 v[8];
        #pragma unroll
        for (int k = 0; k < 8; k++){
            int i4 = base + k * NT + tid;
            v[k] = (i4 < NF4) ? colBase[i4]
                              : make_float4(-1e9f, -1e9f, -1e9f, -1e9f);
        }
        unsigned hm = 0;
        #pragma unroll
        for (int k = 0; k < 8; k++){
            int i4 = base + k * NT + tid;
            int i4m = (i4 < NF4) ? i4 : 0;
            int c = i4m / HWF4;
            int l4 = i4m - c * HWF4;
            float4 xc = ((const float4*)s_xcut)[l4];
            if (v[k].x > xc.x) hm |= 1u << (4*k + 0);
            if (v[k].y > xc.y) hm |= 1u << (4*k + 1);
            if (v[k].z > xc.z) hm |= 1u << (4*k + 2);
            if (v[k].w > xc.w) hm |= 1u << (4*k + 3);
        }
        unsigned h = (unsigned)__popc(hm);
        unsigned incl = h;
        #pragma unroll
        for (int off = 1; off < 32; off <<= 1){
            unsigned t = __shfl_up_sync(0xffffffffu, incl, off);
            if (lane >= off) incl += t;
        }
        unsigned wtot = __shfl_sync(0xffffffffu, incl, 31);
        unsigned wbase = 0;
        if (wtot){
            if (lane == 31) wbase = atomicAdd(&s_nc, wtot);
            wbase = __shfl_sync(0xffffffffu, wbase, 31);
        }
        unsigned p = wbase + incl - h;
        if (hm){
            #pragma unroll
            for (int k = 0; k < 8; k++){
                #pragma unroll
                for (int j = 0; j < 4; j++){
                    if (hm & (1u << (4*k + j))){
                        if (p < CAPL)
                            s_cand[p] = (unsigned)(4 * (base + k * NT + tid) + j);
                        p++;
                    }
                }
            }
        }
    }
    __syncthreads();

    unsigned ncRaw = s_nc;
    bool ovf = (ncRaw > CAPL);
    int nc = ovf ? CAPL : (int)ncRaw;

    // ---- Phase 2: exact eval pass 1 — hist of keys >= 0.5 + per-class max
    if (!ovf){
        for (int i = tid; i < nc; i += NT){
            unsigned e = s_cand[i];
            int c = e / HW;
            int loc = e - c * HW;
            float x = cls[e];
            float sv = __fmul_rn(sig_x(x), s_ctr[loc]);
            unsigned key = __float_as_uint(sv) | 0x80000000u;
            unsigned long long pk = ((unsigned long long)key << 32) | (unsigned)(HW - 1 - loc);
            if (pk > *((volatile unsigned long long*)&s_cls[c]))
                atomicMax(&s_cls[c], pk);
            if (key >= PREKEY){
                unsigned bin = (key - PREKEY) >> 12;
                if (bin > 2047u) bin = 2047u;
                atomicAdd(&s_hist[bin], 1u);
            }
        }
    }
    __syncthreads();

    // ---- Phase 3: per-class guarded dense fallback (max < 0.46 or ovf)
    for (int c = 0; c < NCLS; c++){
        bool need = ovf || ((unsigned)(s_cls[c] >> 32) < KEY046);
        if (need){
            const float* colp = cls + c * HW;
            unsigned long long best = 0ULL;
            for (int loc = tid; loc < HW; loc += NT){
                float sv = __fmul_rn(sig_x(colp[loc]), s_ctr[loc]);
                unsigned key = __float_as_uint(sv) | 0x80000000u;
                unsigned long long pk = ((unsigned long long)key << 32) | (unsigned)(HW - 1 - loc);
                if (pk > best) best = pk;
            }
            #pragma unroll
            for (int off = 16; off; off >>= 1){
                unsigned long long o = __shfl_down_sync(0xffffffffu, best, off);
                if (o > best) best = o;
            }
            if (lane == 0) atomicMax(&s_cls[c], best);
        }
    }
    __syncthreads();

    // ---- Phase 4: threshold
    find_cross2048(s_hist, s_scan, TOPK, &s_b, &s_above, &s_total);
    bool fast = (s_b != 0xFFFFFFFFu) && !ovf;
    if (fast) fast = (s_above + s_hist[s_b] <= BUF);
    unsigned b0f = s_b;
    __syncthreads();

    int cnt;
    if (fast){
        // ---- Phase 5: exact eval pass 2 — collect keys >= T into s_keys
        unsigned T = PREKEY + (b0f << 12);
        for (int base = 0; base < nc; base += NT){
            int i = base + tid;
            bool on = (i < nc);
            unsigned key = 0; int loc = 0, c = 0;
            if (on){
                unsigned e = s_cand[i];
                c = e / HW;
                loc = e - c * HW;
                float x = cls[e];
                float sv = __fmul_rn(sig_x(x), s_ctr[loc]);
                key = __float_as_uint(sv) | 0x80000000u;
            }
            bool take = on && (key >= T);
            unsigned bal = __ballot_sync(0xffffffffu, take);
            if (bal){
                int ldr = __ffs(bal) - 1;
                int basep = 0;
                if (lane == ldr) basep = atomicAdd(&s_cnt, __popc(bal));
                basep = __shfl_sync(0xffffffffu, basep, ldr);
                if (take){
                    int f = loc * NCLS + c;
                    s_keys[basep + __popc(bal & ((1u << lane) - 1u))] =
                        ((unsigned long long)key << 17) | (unsigned)(NENT - f);
                }
            }
        }
        __syncthreads();
        cnt = s_cnt;
    } else {
        // ---- FALLBACK: full exact recompute + radix select (general data)
        unsigned* keys = g_keys + (size_t)n * NENT;
        if (tid == 0) s_tot2 = 0;
        for (int i = tid; i < 2048; i += NT) s_hist[i] = 0u;
        __syncthreads();
        int totL = 0;
        for (int i = tid; i < NENT; i += NT){
            int c = i / HW;
            int loc = i - c * HW;
            float sv = __fmul_rn(sig_x(cls[i]), s_ctr[loc]);
            unsigned ok = __float_as_uint(sv) | 0x80000000u;
            keys[i] = ok;
            if (ok > KTH){ totL++; atomicAdd(&s_hist[(ok >> 15) & 0x7FFu], 1u); }
        }
        #pragma unroll
        for (int off = 16; off; off >>= 1) totL += __shfl_down_sync(0xffffffffu, totL, off);
        if (lane == 0) atomicAdd(&s_tot2, totL);
        if (tid == 0) s_b = 0xFFFFFFFFu;
        __syncthreads();
        int total = s_tot2;

        find_cross2048(s_hist, s_scan, TOPK, &s_b, &s_above, &s_total);
        int mode; unsigned T = 0; int needed = 0;
        if (total < TOPK){
            mode = 2; T = 0u; needed = TOPK - total;
        } else {
            unsigned b0 = s_b;
            unsigned above1 = s_above;
            unsigned c1 = above1 + s_hist[b0];
            __syncthreads();
            if (c1 <= BUF){
                mode = 0; T = TOPBITS | (b0 << 15);
            } else {
                for (int i = tid; i < 2048; i += NT) s_hist[i] = 0u;
                __syncthreads();
                for (int i = tid; i < NENT; i += NT){
                    unsigned ok = keys[i];
                    if (ok > KTH && ((ok >> 15) & 0x7FFu) == b0)
                        atomicAdd(&s_hist[(ok >> 4) & 0x7FFu], 1u);
                }
                __syncthreads();
                find_cross2048(s_hist, s_scan, TOPK - above1, &s_b, &s_above, &s_total);
                unsigned b1 = s_b;
                unsigned above2 = above1 + s_above;
                unsigned c2 = above2 + s_hist[b1];
                __syncthreads();
                if (c2 <= BUF){
                    mode = 0; T = TOPBITS | (b0 << 15) | (b1 << 4);
                } else {
                    if (tid < 16) s_hist[tid] = 0u;
                    __syncthreads();
                    unsigned winhi = (TOPBITS | (b0 << 15) | (b1 << 4)) >> 4;
                    for (int i = tid; i < NENT; i += NT){
                        unsigned ok = keys[i];
                        if (ok > KTH && (ok >> 4) == winhi)
                            atomicAdd(&s_hist[ok & 0xFu], 1u);
                    }
                    __syncthreads();
                    if (tid == 0){
                        unsigned K3 = TOPK - above2, run = 0;
                        for (int b = 15; b >= 0; b--){
                            unsigned h = s_hist[b];
                            if (run + h >= K3){ s_b = (unsigned)b; s_above = run; break; }
                            run += h;
                        }
                    }
                    __syncthreads();
                    unsigned b2 = s_b;
                    unsigned above3 = above2 + s_above;
                    unsigned c3 = above3 + s_hist[b2];
                    __syncthreads();
                    T = TOPBITS | (b0 << 15) | (b1 << 4) | b2;
                    if (c3 <= BUF) mode = 0;
                    else { mode = 1; needed = TOPK - (int)above3; }
                }
            }
        }
        for (int i = tid; i < NENT; i += NT){
            unsigned ok = keys[i];
            bool take = (ok > KTH) && (mode == 1 ? (ok > T) : (ok >= T));
            if (take){
                int c = i / HW;
                int loc = i - c * HW;
                int f = loc * NCLS + c;
                s_keys[atomicAdd(&s_cnt, 1)] = ((unsigned long long)ok << 17) | (unsigned)(NENT - f);
            }
        }
        __syncthreads();
        cnt = s_cnt;
        if (mode != 0){
            if (tid == 0) s_fill = 0;
            __syncthreads();
            unsigned fillHigh = (mode == 1) ? T : 0u;
            for (int fb = 0; fb < NENT; fb += NT){
                int f = fb + tid;
                bool eq = false;
                if (f < NENT){
                    int loc = f / NCLS;
                    int c = f - loc * NCLS;
                    unsigned ok = keys[c * HW + loc];
                    eq = (mode == 1) ? (ok == T) : (ok <= KTH);
                }
                unsigned bal = __ballot_sync(0xffffffffu, eq);
                if (lane == 0) s_wcnt[wrp] = (unsigned)__popc(bal);
                __syncthreads();
                if (tid == 0){
                    unsigned run = (unsigned)s_fill;
                    #pragma unroll
                    for (int i = 0; i < NT/32; i++){ s_woff[i] = run; run += s_wcnt[i]; }
                    s_fill = (int)run;
                }
                __syncthreads();
                if (eq){
                    int rank = (int)s_woff[wrp] + __popc(bal & ((1u << lane) - 1u));
                    if (rank < needed)
                        s_keys[cnt + rank] = ((unsigned long long)fillHigh << 17) | (unsigned)(NENT - f);
                }
                if (s_fill >= needed) break;
            }
            cnt = TOPK;
            __syncthreads();
        }
    }

    // ---- Phase 6: prune to <= 1024 (rare); write into s_srt (overlays s_cand)
    if (cnt > SRT){
        unsigned long long hi = 0;
        int K = TOPK, above = 0;
        unsigned long long thresholdP = 0;
        #pragma unroll 1
        for (int l = 0; l < 5; l++){
            const int sh = (l==0)?38:(l==1)?27:(l==2)?16:(l==3)?5:0;
            const int wb = (l==4)?5:11;
            for (int i = tid; i < 2048; i += NT) s_hist[i] = 0u;
            __syncthreads();
            for (int i = tid; i < cnt; i += NT){
                unsigned long long p = s_keys[i];
                if ((p >> (sh + wb)) == hi)
                    atomicAdd(&s_hist[(unsigned)((p >> sh) & ((1u << wb) - 1u))], 1u);
            }
            __syncthreads();
            find_cross2048(s_hist, s_scan, (unsigned)K, &s_b, &s_above, &s_total);
            unsigned b = s_b, aw = s_above, hb = s_hist[b];
            __syncthreads();
            if (above + (int)aw + (int)hb <= SRT){
                thresholdP = ((hi << wb) | b) << sh;
                break;
            }
            above += (int)aw; K -= (int)aw; hi = (hi << wb) | b;
        }
        for (int base = 0; base < cnt; base += NT){
            int i = base + tid;
            bool take = (i < cnt) && (s_keys[i] >= thresholdP);
            unsigned bal = __ballot_sync(0xffffffffu, take);
            if (bal){
                int ldr = __ffs(bal) - 1;
                int basep = 0;
                if (lane == ldr) basep = atomicAdd(&s_cnt2, __popc(bal));
                basep = __shfl_sync(0xffffffffu, basep, ldr);
                if (take)
                    s_srt[basep + __popc(bal & ((1u << lane) - 1u))] = s_keys[i];
            }
        }
        __syncthreads();
        int c2 = s_cnt2;
        for (int i = tid; i < SRT; i += NT)
            if (i >= c2) s_srt[i] = 0ULL;
    } else {
        for (int i = tid; i < SRT; i += NT)
            s_srt[i] = (i < cnt) ? s_keys[i] : 0ULL;
    }
    __syncthreads();

    // ---- Phase 7: bitonic sort, descending, 1024 u64
    for (unsigned k = 2; k <= SRT; k <<= 1){
        for (unsigned j = k >> 1; j > 0; j >>= 1){
            #pragma unroll
            for (int t = 0; t < SRT/NT; t++){
                int i = tid + t * NT;
                unsigned ixj = (unsigned)i ^ j;
                if (ixj > (unsigned)i){
                    unsigned long long a = s_srt[i];
                    unsigned long long b = s_srt[ixj];
                    bool desc = ((i & k) == 0);
                    if (desc ? (a < b) : (a > b)){
                        s_srt[i] = b; s_srt[ixj] = a;
                    }
                }
            }
            __syncthreads();
        }
    }

    // ---- Phase 8: decode + write outputs (rounding-pinned; verified bit-exact)
    const size_t detB = 0;
    const size_t scB  = (size_t)NIMG * TOPK * 4;
    const size_t lbB  = scB + (size_t)NIMG * TOPK;
    const size_t vaB  = lbB + (size_t)NIMG * TOPK;
    const size_t hdB  = vaB + (size_t)NIMG * TOPK;
    const size_t hsB  = hdB + (size_t)NIMG * NCLS * 4;
    const float bx = gbox[n*4+0], by = gbox[n*4+1];
    const float sx = __fsub_rn(gbox[n*4+2], bx);
    const float sy = __fsub_rn(gbox[n*4+3], by);
    const float ps = gps[n];

    for (int i = tid; i < TOPK; i += NT){
        unsigned long long e = s_srt[i];
        unsigned ok = (unsigned)(e >> 17);
        int f = NENT - (int)(e & 0x1FFFFu);
        int loc = f / NCLS;
        int c = f - loc * NCLS;
        int h = loc / RES, w = loc - h * RES;
        float lx = w + 0.5f, ly = h + 0.5f;
        float r0 = reg[loc], r1 = reg[HW + loc], r2 = reg[2*HW + loc], r3 = reg[3*HW + loc];
        float x1 = __fadd_rn(__fmul_rn(__fdiv_rn(__fsub_rn(lx, r0), 56.0f), sx), bx);
        float y1 = __fadd_rn(__fmul_rn(__fdiv_rn(__fsub_rn(ly, r1), 56.0f), sy), by);
        float x2 = __fadd_rn(__fmul_rn(__fdiv_rn(__fadd_rn(lx, r2), 56.0f), sx), bx);
        float y2 = __fadd_rn(__fmul_rn(__fdiv_rn(__fadd_rn(ly, r3), 56.0f), sy), by);
        x1 = fminf(fmaxf(x1, 0.0f), 1332.0f);
        x2 = fminf(fmaxf(x2, 0.0f), 1332.0f);
        y1 = fminf(fmaxf(y1, 0.0f),  799.0f);
        y2 = fminf(fmaxf(y2, 0.0f),  799.0f);
        bool valid = (ok > KTH) && (__fsub_rn(x2, x1) >= 0.0f) && (__fsub_rn(y2, y1) >= 0.0f);
        float val = __uint_as_float(ok ^ 0x80000000u);
        float sc = valid ? __fsqrt_rn(__fmul_rn(__fsqrt_rn(val), ps)) : 0.0f;
        size_t row = (size_t)n * TOPK + i;
        out[detB + row*4 + 0] = x1;
        out[detB + row*4 + 1] = y1;
        out[detB + row*4 + 2] = x2;
        out[detB + row*4 + 3] = y2;
        out[scB + row] = sc;
        out[lbB + row] = (float)(c + 2);
        out[vaB + row] = valid ? 1.0f : 0.0f;
    }

    if (tid < NCLS){
        unsigned long long e = s_cls[tid];
        unsigned ok = (unsigned)(e >> 32);
        int loc = HW - 1 - (int)(e & 0xFFFFFFFFu);
        int h = loc / RES, w = loc - h * RES;
        float lx = w + 0.5f, ly = h + 0.5f;
        float r0 = reg[loc], r1 = reg[HW + loc], r2 = reg[2*HW + loc], r3 = reg[3*HW + loc];
        float x1 = __fadd_rn(__fmul_rn(__fdiv_rn(__fsub_rn(lx, r0), 56.0f), sx), bx);
        float y1 = __fadd_rn(__fmul_rn(__fdiv_rn(__fsub_rn(ly, r1), 56.0f), sy), by);
        float x2 = __fadd_rn(__fmul_rn(__fdiv_rn(__fadd_rn(lx, r2), 56.0f), sx), bx);
        float y2 = __fadd_rn(__fmul_rn(__fdiv_rn(__fadd_rn(ly, r3), 56.0f), sy), by);
        float hv = __uint_as_float(ok ^ 0x80000000u);
        float hs = (hv >= 0.9f) ? __fsqrt_rn(__fmul_rn(__fsqrt_rn(hv), ps)) : 0.0f;
        size_t rr = (size_t)n * NCLS + tid;
        out[hdB + rr*4 + 0] = x1;
        out[hdB + rr*4 + 1] = y1;
        out[hdB + rr*4 + 2] = x2;
        out[hdB + rr*4 + 3] = y2;
        out[hsB + rr] = hs;
    }
}

extern "C" void kernel_launch(void* const* d_in, const int* in_sizes, int n_in,
                              void* d_out, int out_size)
{
    const float *bcls = nullptr, *breg = nullptr, *bctr = nullptr,
                *bbox = nullptr, *bps = nullptr;
    for (int i = 0; i < n_in; i++){
        switch (in_sizes[i]){
            case 32112640: bcls = (const float*)d_in[i]; break;
            case 6422528:  breg = (const float*)d_in[i]; break;
            case 1605632:  bctr = (const float*)d_in[i]; break;
            case 2048:     bbox = (const float*)d_in[i]; break;
            case 512:      bps  = (const float*)d_in[i]; break;
            default: break;
        }
    }
    (void)out_size;
    cudaFuncSetAttribute(post_fused, cudaFuncAttributeMaxDynamicSharedMemorySize,
                         SMEM_TOTAL);
    post_fused<<<NIMG, NT, SMEM_TOTAL>>>(bcls, breg, bctr, bbox, bps, (float*)d_out);
}